// round 1
// baseline (speedup 1.0000x reference)
#include <cuda_runtime.h>
#include <math.h>

// Problem constants
#define BB   4
#define SS   2048
#define DD   768
#define HH   12
#define DHD  64
#define DFF  3072
#define MROWS (BB*SS)          // 8192

// -------- scratch (device globals; no allocations allowed) --------
static __device__ float g_q  [(size_t)BB*SS*DD];
static __device__ float g_k  [(size_t)BB*SS*DD];
static __device__ float g_v  [(size_t)BB*SS*DD];
static __device__ float g_ctx[(size_t)BB*SS*DD];
static __device__ float g_tmp[(size_t)BB*SS*DD];
static __device__ float g_h  [(size_t)BB*SS*DD];
static __device__ float g_ff1[(size_t)MROWS*DFF];
static __device__ float g_scores[(size_t)BB*HH*SS*SS];   // ~805 MB

__device__ __forceinline__ float gelu_exact(float x) {
    return 0.5f * x * (1.0f + erff(x * 0.7071067811865476f));
}

// ---------------- generic tiled SGEMM ----------------
// C[M,N] = alpha * A[M,K] @ op(B) (+bias) (+gelu)
// TB=false: B is [K,N] row-major. TB=true: B is [N,K] row-major (C=A@B^T).
// Batched via blockIdx.z: off = (z/Hn)*s?b + (z%Hn)*s?h.
template<int BM,int BN,int BK,int TM,int TN,bool TB,int EPI>
__global__ __launch_bounds__((BM/TM)*(BN/TN))
void sgemm_k(const float* __restrict__ A, const float* __restrict__ Bm,
             float* __restrict__ C, const float* __restrict__ bias,
             int M,int N,int K,int lda,int ldb,int ldc,float alpha,
             long long sAb,long long sAh,long long sBb,long long sBh,
             long long sCb,long long sCh,int Hn)
{
    constexpr int NT = (BM/TM)*(BN/TN);
    __shared__ float As[BK][BM];
    __shared__ float Bs[BK][BN];

    const int t  = threadIdx.x;
    const int bz = blockIdx.z;
    const int bb = bz / Hn, hh = bz % Hn;
    A  += (size_t)bb*sAb + (size_t)hh*sAh;
    Bm += (size_t)bb*sBb + (size_t)hh*sBh;
    C  += (size_t)bb*sCb + (size_t)hh*sCh;

    const int m0 = blockIdx.y * BM;
    const int n0 = blockIdx.x * BN;
    const int tx = t % (BN/TN);
    const int ty = t / (BN/TN);

    float acc[TM][TN];
    #pragma unroll
    for (int i=0;i<TM;i++)
        #pragma unroll
        for (int j=0;j<TN;j++) acc[i][j]=0.f;

    for (int k0=0; k0<K; k0+=BK) {
        // ---- load A tile -> As[k][m] (transposed in smem) ----
        constexpr int L4A = (BM*BK)/(4*NT);
        #pragma unroll
        for (int l=0;l<L4A;l++){
            int fid = t + l*NT;
            int m   = fid / (BK/4);
            int kq  = (fid % (BK/4)) * 4;
            float4 v = *reinterpret_cast<const float4*>(A + (size_t)(m0+m)*lda + k0 + kq);
            As[kq+0][m]=v.x; As[kq+1][m]=v.y; As[kq+2][m]=v.z; As[kq+3][m]=v.w;
        }
        // ---- load B tile -> Bs[k][n] ----
        if (!TB) {
            constexpr int L4B = (BK*BN)/(4*NT);
            #pragma unroll
            for (int l=0;l<L4B;l++){
                int fid = t + l*NT;
                int kr  = fid / (BN/4);
                int nq  = (fid % (BN/4)) * 4;
                *reinterpret_cast<float4*>(&Bs[kr][nq]) =
                    *reinterpret_cast<const float4*>(Bm + (size_t)(k0+kr)*ldb + n0 + nq);
            }
        } else {
            constexpr int L4B = (BN*BK)/(4*NT);
            #pragma unroll
            for (int l=0;l<L4B;l++){
                int fid = t + l*NT;
                int n   = fid / (BK/4);
                int kq  = (fid % (BK/4)) * 4;
                float4 v = *reinterpret_cast<const float4*>(Bm + (size_t)(n0+n)*ldb + k0 + kq);
                Bs[kq+0][n]=v.x; Bs[kq+1][n]=v.y; Bs[kq+2][n]=v.z; Bs[kq+3][n]=v.w;
            }
        }
        __syncthreads();

        // ---- compute ----
        #pragma unroll
        for (int kk=0;kk<BK;kk++){
            float a[TM], b[TN];
            #pragma unroll
            for (int i=0;i<TM;i+=4)
                *reinterpret_cast<float4*>(&a[i]) =
                    *reinterpret_cast<const float4*>(&As[kk][ty*TM+i]);
            #pragma unroll
            for (int j=0;j<TN;j+=4)
                *reinterpret_cast<float4*>(&b[j]) =
                    *reinterpret_cast<const float4*>(&Bs[kk][tx*TN+j]);
            #pragma unroll
            for (int i=0;i<TM;i++)
                #pragma unroll
                for (int j=0;j<TN;j++)
                    acc[i][j] = fmaf(a[i], b[j], acc[i][j]);
        }
        __syncthreads();
    }

    // ---- epilogue ----
    #pragma unroll
    for (int i=0;i<TM;i++){
        size_t crow = (size_t)(m0 + ty*TM + i)*ldc + n0 + tx*TN;
        #pragma unroll
        for (int j=0;j<TN;j+=4){
            float4 v;
            float x0 = acc[i][j+0]*alpha, x1 = acc[i][j+1]*alpha;
            float x2 = acc[i][j+2]*alpha, x3 = acc[i][j+3]*alpha;
            if (EPI >= 1) {
                int nb = n0 + tx*TN + j;
                x0 += bias[nb+0]; x1 += bias[nb+1]; x2 += bias[nb+2]; x3 += bias[nb+3];
            }
            if (EPI == 2) {
                x0 = gelu_exact(x0); x1 = gelu_exact(x1);
                x2 = gelu_exact(x2); x3 = gelu_exact(x3);
            }
            v.x=x0; v.y=x1; v.z=x2; v.w=x3;
            *reinterpret_cast<float4*>(C + crow + j) = v;
        }
    }
}

// ---------------- block reduce ----------------
__device__ __forceinline__ float block_reduce(float val, bool ismax) {
    __shared__ float sh[32];
    int lane = threadIdx.x & 31;
    int w    = threadIdx.x >> 5;
    #pragma unroll
    for (int off=16; off>0; off>>=1) {
        float o = __shfl_xor_sync(0xffffffffu, val, off);
        val = ismax ? fmaxf(val, o) : (val + o);
    }
    if (lane == 0) sh[w] = val;
    __syncthreads();
    int nw = blockDim.x >> 5;
    if (w == 0) {
        float v = (lane < nw) ? sh[lane] : (ismax ? -3.4e38f : 0.f);
        #pragma unroll
        for (int off=16; off>0; off>>=1) {
            float o = __shfl_xor_sync(0xffffffffu, v, off);
            v = ismax ? fmaxf(v, o) : (v + o);
        }
        if (lane == 0) sh[0] = v;
    }
    __syncthreads();
    float r = sh[0];
    __syncthreads();
    return r;
}

// ---------------- softmax over rows of length 2048 ----------------
__global__ __launch_bounds__(256) void softmax_k(float* __restrict__ s)
{
    const int n = SS;                       // 2048
    size_t base = (size_t)blockIdx.x * n;
    int t = threadIdx.x;
    float v[8];
    float mx = -3.4e38f;
    #pragma unroll
    for (int i=0;i<8;i++){ v[i] = s[base + t + i*256]; mx = fmaxf(mx, v[i]); }
    mx = block_reduce(mx, true);
    float sum = 0.f;
    #pragma unroll
    for (int i=0;i<8;i++){ v[i] = expf(v[i]-mx); sum += v[i]; }
    sum = block_reduce(sum, false);
    float inv = 1.f / sum;
    #pragma unroll
    for (int i=0;i<8;i++) s[base + t + i*256] = v[i]*inv;
}

// ---------------- residual add + layernorm ----------------
__global__ __launch_bounds__(256) void add_ln_k(
    const float* __restrict__ x, const float* __restrict__ res,
    const float* __restrict__ g, const float* __restrict__ b,
    float* __restrict__ y)
{
    size_t base = (size_t)blockIdx.x * DD;
    int t = threadIdx.x;
    float v[3];
    float s = 0.f;
    #pragma unroll
    for (int i=0;i<3;i++){
        int c = t + i*256;
        v[i] = x[base + c] + res[base + c];
        s += v[i];
    }
    s = block_reduce(s, false);
    float mu = s * (1.0f/DD);
    float q = 0.f;
    #pragma unroll
    for (int i=0;i<3;i++){ float d = v[i]-mu; q += d*d; }
    q = block_reduce(q, false);
    float rstd = rsqrtf(q * (1.0f/DD) + 1e-5f);
    #pragma unroll
    for (int i=0;i<3;i++){
        int c = t + i*256;
        y[base + c] = (v[i]-mu)*rstd*g[c] + b[c];
    }
}

// ---------------- launch ----------------
extern "C" void kernel_launch(void* const* d_in, const int* in_sizes, int n_in,
                              void* d_out, int out_size)
{
    const float* Q   = (const float*)d_in[0];
    const float* K   = (const float*)d_in[1];
    const float* V   = (const float*)d_in[2];
    const float* Wq  = (const float*)d_in[3];
    const float* bq  = (const float*)d_in[4];
    const float* Wk  = (const float*)d_in[5];
    const float* bk  = (const float*)d_in[6];
    const float* Wv  = (const float*)d_in[7];
    const float* bv  = (const float*)d_in[8];
    const float* Wo  = (const float*)d_in[9];
    const float* bo  = (const float*)d_in[10];
    const float* lng = (const float*)d_in[11];
    const float* lnb = (const float*)d_in[12];
    const float* W1  = (const float*)d_in[13];
    const float* b1  = (const float*)d_in[14];
    const float* W2  = (const float*)d_in[15];
    const float* b2  = (const float*)d_in[16];
    float* out = (float*)d_out;

    float *q, *k, *v, *ctx, *tmp, *h, *ff1, *sc;
    cudaGetSymbolAddress((void**)&q,   g_q);
    cudaGetSymbolAddress((void**)&k,   g_k);
    cudaGetSymbolAddress((void**)&v,   g_v);
    cudaGetSymbolAddress((void**)&ctx, g_ctx);
    cudaGetSymbolAddress((void**)&tmp, g_tmp);
    cudaGetSymbolAddress((void**)&h,   g_h);
    cudaGetSymbolAddress((void**)&ff1, g_ff1);
    cudaGetSymbolAddress((void**)&sc,  g_scores);

    const long long ZL = 0;

    // 1) QKV projections: [8192,768] @ [768,768] + bias
    {
        dim3 grid(DD/128, MROWS/128, 1);
        sgemm_k<128,128,16,8,8,false,1><<<grid,256>>>(Q, Wq, q, bq,
            MROWS, DD, DD, DD, DD, DD, 1.f, ZL,ZL,ZL,ZL,ZL,ZL, 1);
        sgemm_k<128,128,16,8,8,false,1><<<grid,256>>>(K, Wk, k, bk,
            MROWS, DD, DD, DD, DD, DD, 1.f, ZL,ZL,ZL,ZL,ZL,ZL, 1);
        sgemm_k<128,128,16,8,8,false,1><<<grid,256>>>(V, Wv, v, bv,
            MROWS, DD, DD, DD, DD, DD, 1.f, ZL,ZL,ZL,ZL,ZL,ZL, 1);
    }

    // 2) scores = q @ k^T * 1/8 per (b,h): M=N=2048, K=64
    {
        dim3 grid(SS/128, SS/128, BB*HH);
        sgemm_k<128,128,16,8,8,true,0><<<grid,256>>>(q, k, sc, nullptr,
            SS, SS, DHD, DD, DD, SS, 0.125f,
            (long long)SS*DD, (long long)DHD,       // A strides (b,h)
            (long long)SS*DD, (long long)DHD,       // B strides
            (long long)HH*SS*SS, (long long)SS*SS,  // C strides
            HH);
    }

    // 3) softmax rows
    softmax_k<<<BB*HH*SS, 256>>>(sc);

    // 4) ctx = attn @ v per (b,h): M=2048, N=64, K=2048
    {
        dim3 grid(1, SS/64, BB*HH);
        sgemm_k<64,64,16,4,4,false,0><<<grid,256>>>(sc, v, ctx, nullptr,
            SS, DHD, SS, SS, DD, DD, 1.f,
            (long long)HH*SS*SS, (long long)SS*SS,
            (long long)SS*DD, (long long)DHD,
            (long long)SS*DD, (long long)DHD,
            HH);
    }

    // 5) attn_out = ctx @ Wo + bo
    {
        dim3 grid(DD/128, MROWS/128, 1);
        sgemm_k<128,128,16,8,8,false,1><<<grid,256>>>(ctx, Wo, tmp, bo,
            MROWS, DD, DD, DD, DD, DD, 1.f, ZL,ZL,ZL,ZL,ZL,ZL, 1);
    }

    // 6) h = LN(Q + attn_out)
    add_ln_k<<<MROWS, 256>>>(tmp, Q, lng, lnb, h);

    // 7) ff1 = gelu(h @ W1 + b1): [8192,768]@[768,3072]
    {
        dim3 grid(DFF/128, MROWS/128, 1);
        sgemm_k<128,128,16,8,8,false,2><<<grid,256>>>(h, W1, ff1, b1,
            MROWS, DFF, DD, DD, DFF, DFF, 1.f, ZL,ZL,ZL,ZL,ZL,ZL, 1);
    }

    // 8) out = ff1 @ W2 + b2: [8192,3072]@[3072,768]
    {
        dim3 grid(DD/128, MROWS/128, 1);
        sgemm_k<128,128,16,8,8,false,1><<<grid,256>>>(ff1, W2, out, b2,
            MROWS, DD, DFF, DFF, DD, DD, 1.f, ZL,ZL,ZL,ZL,ZL,ZL, 1);
    }
}

// round 3
// speedup vs baseline: 2.4428x; 2.4428x over previous
#include <cuda_runtime.h>
#include <math.h>
#include <stdint.h>

// Problem constants
#define BB   4
#define SS   2048
#define DD   768
#define HH   12
#define DHD  64
#define DFF  3072
#define MROWS (BB*SS)          // 8192

// -------- scratch (device globals; no allocations allowed) --------
static __device__ __align__(16) float g_q  [(size_t)BB*SS*DD];
static __device__ __align__(16) float g_k  [(size_t)BB*SS*DD];
static __device__ __align__(16) float g_v  [(size_t)BB*SS*DD];
static __device__ __align__(16) float g_vT [(size_t)BB*HH*DHD*SS];
static __device__ __align__(16) float g_ctx[(size_t)BB*SS*DD];
static __device__ __align__(16) float g_tmp[(size_t)BB*SS*DD];
static __device__ __align__(16) float g_h  [(size_t)BB*SS*DD];
static __device__ __align__(16) float g_ff1[(size_t)MROWS*DFF];
static __device__ __align__(16) float g_scores[(size_t)BB*HH*SS*SS];   // ~805 MB
static __device__ __align__(16) float g_wqT[(size_t)DD*DD];
static __device__ __align__(16) float g_wkT[(size_t)DD*DD];
static __device__ __align__(16) float g_wvT[(size_t)DD*DD];
static __device__ __align__(16) float g_woT[(size_t)DD*DD];
static __device__ __align__(16) float g_w1T[(size_t)DFF*DD];
static __device__ __align__(16) float g_w2T[(size_t)DD*DFF];

__device__ __forceinline__ float gelu_exact(float x) {
    return 0.5f * x * (1.0f + erff(x * 0.7071067811865476f));
}

// ---------------- mma.sync tf32 helpers ----------------
__device__ __forceinline__ uint32_t f2tf(float x) {
    uint32_t u = __float_as_uint(x);
    asm("cvt.rna.tf32.f32 %0, %0;" : "+r"(u));
    return u;
}
__device__ __forceinline__ void mma8(float* c, const uint32_t* a, const uint32_t* b) {
    asm volatile("mma.sync.aligned.m16n8k8.row.col.f32.tf32.tf32.f32 "
        "{%0,%1,%2,%3}, {%4,%5,%6,%7}, {%8,%9}, {%0,%1,%2,%3};"
        : "+f"(c[0]), "+f"(c[1]), "+f"(c[2]), "+f"(c[3])
        : "r"(a[0]), "r"(a[1]), "r"(a[2]), "r"(a[3]), "r"(b[0]), "r"(b[1]));
}
template<int N> __device__ __forceinline__ void cp_wait() {
    asm volatile("cp.async.wait_group %0;" :: "n"(N));
}
#define CP_COMMIT() asm volatile("cp.async.commit_group;")

// stage loader: A tile [BM x 16], B tile [BN x 16], both K-contiguous rows
template<int BM, int BN>
__device__ __forceinline__ void load_tiles(float* sA, float* sB,
    const float* __restrict__ Ab, const float* __restrict__ Bb,
    int lda, int ldb, int kt, int st, int tid)
{
    constexpr int PITCH = 20;
    constexpr int ACH = (BM*4)/256;
    constexpr int BCH = (BN*4)/256;
    float* dA = sA + (size_t)st*BM*PITCH;
    #pragma unroll
    for (int l = 0; l < ACH; l++) {
        int ci = tid + l*256;
        int r = ci >> 2, c = ci & 3;
        uint32_t d = (uint32_t)__cvta_generic_to_shared(dA + r*PITCH + c*4);
        asm volatile("cp.async.cg.shared.global [%0], [%1], 16;"
            :: "r"(d), "l"(Ab + (size_t)r*lda + kt*16 + c*4));
    }
    float* dB = sB + (size_t)st*BN*PITCH;
    #pragma unroll
    for (int l = 0; l < BCH; l++) {
        int ci = tid + l*256;
        int r = ci >> 2, c = ci & 3;
        uint32_t d = (uint32_t)__cvta_generic_to_shared(dB + r*PITCH + c*4);
        asm volatile("cp.async.cg.shared.global [%0], [%1], 16;"
            :: "r"(d), "l"(Bb + (size_t)r*ldb + kt*16 + c*4));
    }
}

// =================== tf32 mma.sync GEMM ===================
// C[M,N] = alpha * A[M,K] @ B[N,K]^T (+bias)(+gelu). Batched via blockIdx.z.
// BK = 16, 4-stage cp.async pipeline, 256 threads, warp tile WM x WN.
template<int BM, int BN, int WM, int WN, int EPI>
__global__ __launch_bounds__(256, 2)
void mma_gemm(const float* __restrict__ A, const float* __restrict__ Bm,
              float* __restrict__ C, const float* __restrict__ bias,
              int K, int lda, int ldb, int ldc, float alpha, int Hn,
              int axh, int ayb, int ayh,
              int bxh, int byb, int byh,
              long long czb, long long czh)
{
    constexpr int S = 4;
    constexpr int PITCH = 20;
    constexpr int WARPS_N = BN/WN;
    constexpr int MT = WM/16, NT = WN/8;

    extern __shared__ float sm[];
    float* sA = sm;
    float* sB = sm + (size_t)S*BM*PITCH;

    const int tid = threadIdx.x;
    const int z = blockIdx.z, bb = z / Hn, hh = z % Hn;
    const int m0 = blockIdx.y * BM, n0 = blockIdx.x * BN;

    const float* Ab = A  + (size_t)(ayb*bb + ayh*hh + m0)*lda + axh*hh;
    const float* Bb = Bm + (size_t)(byb*bb + byh*hh + n0)*ldb + bxh*hh;

    const int KT = K / 16;

    // prologue: fill S-1 stages
    #pragma unroll
    for (int s = 0; s < S-1; s++) {
        if (s < KT) load_tiles<BM,BN>(sA, sB, Ab, Bb, lda, ldb, s, s, tid);
        CP_COMMIT();
    }

    const int wid = tid >> 5, lane = tid & 31;
    const int wm = (wid / WARPS_N) * WM;
    const int wn = (wid % WARPS_N) * WN;
    const int qr = lane >> 2, qc = lane & 3;

    float acc[MT][NT][4];
    #pragma unroll
    for (int i = 0; i < MT; i++)
        #pragma unroll
        for (int j = 0; j < NT; j++)
            #pragma unroll
            for (int e = 0; e < 4; e++) acc[i][j][e] = 0.f;

    for (int kt = 0; kt < KT; kt++) {
        cp_wait<S-2>();
        __syncthreads();
        const int nk = kt + S - 1;
        if (nk < KT) load_tiles<BM,BN>(sA, sB, Ab, Bb, lda, ldb, nk, nk % S, tid);
        CP_COMMIT();

        const float* As = sA + (size_t)(kt % S)*BM*PITCH;
        const float* Bs = sB + (size_t)(kt % S)*BN*PITCH;
        #pragma unroll
        for (int ks = 0; ks < 2; ks++) {
            uint32_t af[MT][4], bf[NT][2];
            #pragma unroll
            for (int mt = 0; mt < MT; mt++) {
                const float* p = As + (size_t)(wm + mt*16 + qr)*PITCH + ks*8 + qc;
                af[mt][0] = f2tf(p[0]);
                af[mt][1] = f2tf(p[8*PITCH]);
                af[mt][2] = f2tf(p[4]);
                af[mt][3] = f2tf(p[8*PITCH + 4]);
            }
            #pragma unroll
            for (int nt = 0; nt < NT; nt++) {
                const float* p = Bs + (size_t)(wn + nt*8 + qr)*PITCH + ks*8 + qc;
                bf[nt][0] = f2tf(p[0]);
                bf[nt][1] = f2tf(p[4]);
            }
            #pragma unroll
            for (int mt = 0; mt < MT; mt++)
                #pragma unroll
                for (int nt = 0; nt < NT; nt++)
                    mma8(acc[mt][nt], af[mt], bf[nt]);
        }
    }

    // ---- epilogue ----
    float* Cb = C + (size_t)czb*bb + (size_t)czh*hh;
    #pragma unroll
    for (int mt = 0; mt < MT; mt++) {
        #pragma unroll
        for (int nt = 0; nt < NT; nt++) {
            const int cc = n0 + wn + nt*8 + qc*2;
            float b0 = 0.f, b1 = 0.f;
            if (EPI >= 1) { b0 = __ldg(&bias[cc]); b1 = __ldg(&bias[cc+1]); }
            float x0 = acc[mt][nt][0]*alpha + b0;
            float x1 = acc[mt][nt][1]*alpha + b1;
            float x2 = acc[mt][nt][2]*alpha + b0;
            float x3 = acc[mt][nt][3]*alpha + b1;
            if (EPI == 2) {
                x0 = gelu_exact(x0); x1 = gelu_exact(x1);
                x2 = gelu_exact(x2); x3 = gelu_exact(x3);
            }
            const size_t r0 = (size_t)(m0 + wm + mt*16 + qr);
            *reinterpret_cast<float2*>(Cb + r0*ldc + cc)     = make_float2(x0, x1);
            *reinterpret_cast<float2*>(Cb + (r0+8)*ldc + cc) = make_float2(x2, x3);
        }
    }
}

// =================== transposes ===================
__global__ __launch_bounds__(256) void transpose_k(const float* __restrict__ src,
                                                   float* __restrict__ dst, int R, int C)
{
    __shared__ float tile[32][33];
    const int c0 = blockIdx.x*32, r0 = blockIdx.y*32;
    const int x = threadIdx.x, y = threadIdx.y;
    #pragma unroll
    for (int i = 0; i < 32; i += 8) tile[y+i][x] = src[(size_t)(r0+y+i)*C + c0+x];
    __syncthreads();
    #pragma unroll
    for (int i = 0; i < 32; i += 8) dst[(size_t)(c0+y+i)*R + r0+x] = tile[x][y+i];
}

// v [b*2048+s][h*64+d] -> vT [(b*12+h)*64+d][s]
__global__ __launch_bounds__(256) void vtrans_k(const float* __restrict__ v,
                                                float* __restrict__ vt)
{
    __shared__ float tile[32][33];
    const int z = blockIdx.z, bb = z/HH, hh = z%HH;
    const int s0 = blockIdx.x*32, d0 = blockIdx.y*32;
    const int x = threadIdx.x, y = threadIdx.y;
    #pragma unroll
    for (int i = 0; i < 32; i += 8)
        tile[y+i][x] = v[(size_t)(bb*SS + s0 + y+i)*DD + hh*DHD + d0 + x];
    __syncthreads();
    #pragma unroll
    for (int i = 0; i < 32; i += 8)
        vt[(size_t)(z*DHD + d0 + y+i)*SS + s0 + x] = tile[x][y+i];
}

// =================== block reduce / softmax / LN ===================
__device__ __forceinline__ float block_reduce(float val, bool ismax) {
    __shared__ float sh[32];
    int lane = threadIdx.x & 31, w = threadIdx.x >> 5;
    #pragma unroll
    for (int off=16; off>0; off>>=1) {
        float o = __shfl_xor_sync(0xffffffffu, val, off);
        val = ismax ? fmaxf(val, o) : (val + o);
    }
    if (lane == 0) sh[w] = val;
    __syncthreads();
    int nw = blockDim.x >> 5;
    if (w == 0) {
        float v = (lane < nw) ? sh[lane] : (ismax ? -3.4e38f : 0.f);
        #pragma unroll
        for (int off=16; off>0; off>>=1) {
            float o = __shfl_xor_sync(0xffffffffu, v, off);
            v = ismax ? fmaxf(v, o) : (v + o);
        }
        if (lane == 0) sh[0] = v;
    }
    __syncthreads();
    float r = sh[0];
    __syncthreads();
    return r;
}

__global__ __launch_bounds__(256) void softmax_k(float* __restrict__ s)
{
    size_t base = (size_t)blockIdx.x * SS;
    int t = threadIdx.x;
    float v[8];
    float mx = -3.4e38f;
    #pragma unroll
    for (int i=0;i<8;i++){ v[i] = s[base + t + i*256]; mx = fmaxf(mx, v[i]); }
    mx = block_reduce(mx, true);
    float sum = 0.f;
    #pragma unroll
    for (int i=0;i<8;i++){ v[i] = expf(v[i]-mx); sum += v[i]; }
    sum = block_reduce(sum, false);
    float inv = 1.f / sum;
    #pragma unroll
    for (int i=0;i<8;i++) s[base + t + i*256] = v[i]*inv;
}

__global__ __launch_bounds__(256) void add_ln_k(
    const float* __restrict__ x, const float* __restrict__ res,
    const float* __restrict__ g, const float* __restrict__ b,
    float* __restrict__ y)
{
    size_t base = (size_t)blockIdx.x * DD;
    int t = threadIdx.x;
    float v[3];
    float s = 0.f;
    #pragma unroll
    for (int i=0;i<3;i++){
        int c = t + i*256;
        v[i] = x[base + c] + res[base + c];
        s += v[i];
    }
    s = block_reduce(s, false);
    float mu = s * (1.0f/DD);
    float q = 0.f;
    #pragma unroll
    for (int i=0;i<3;i++){ float d = v[i]-mu; q += d*d; }
    q = block_reduce(q, false);
    float rstd = rsqrtf(q * (1.0f/DD) + 1e-5f);
    #pragma unroll
    for (int i=0;i<3;i++){
        int c = t + i*256;
        y[base + c] = (v[i]-mu)*rstd*g[c] + b[c];
    }
}

// =================== launch ===================
extern "C" void kernel_launch(void* const* d_in, const int* in_sizes, int n_in,
                              void* d_out, int out_size)
{
    const float* Q   = (const float*)d_in[0];
    const float* K   = (const float*)d_in[1];
    const float* V   = (const float*)d_in[2];
    const float* Wq  = (const float*)d_in[3];
    const float* bq  = (const float*)d_in[4];
    const float* Wk  = (const float*)d_in[5];
    const float* bk  = (const float*)d_in[6];
    const float* Wv  = (const float*)d_in[7];
    const float* bv  = (const float*)d_in[8];
    const float* Wo  = (const float*)d_in[9];
    const float* bo  = (const float*)d_in[10];
    const float* lng = (const float*)d_in[11];
    const float* lnb = (const float*)d_in[12];
    const float* W1  = (const float*)d_in[13];
    const float* b1  = (const float*)d_in[14];
    const float* W2  = (const float*)d_in[15];
    const float* b2  = (const float*)d_in[16];
    float* out = (float*)d_out;

    float *q,*k,*v,*vT,*ctx,*tmp,*h,*ff1,*sc,*wqT,*wkT,*wvT,*woT,*w1T,*w2T;
    cudaGetSymbolAddress((void**)&q,   g_q);
    cudaGetSymbolAddress((void**)&k,   g_k);
    cudaGetSymbolAddress((void**)&v,   g_v);
    cudaGetSymbolAddress((void**)&vT,  g_vT);
    cudaGetSymbolAddress((void**)&ctx, g_ctx);
    cudaGetSymbolAddress((void**)&tmp, g_tmp);
    cudaGetSymbolAddress((void**)&h,   g_h);
    cudaGetSymbolAddress((void**)&ff1, g_ff1);
    cudaGetSymbolAddress((void**)&sc,  g_scores);
    cudaGetSymbolAddress((void**)&wqT, g_wqT);
    cudaGetSymbolAddress((void**)&wkT, g_wkT);
    cudaGetSymbolAddress((void**)&wvT, g_wvT);
    cudaGetSymbolAddress((void**)&woT, g_woT);
    cudaGetSymbolAddress((void**)&w1T, g_w1T);
    cudaGetSymbolAddress((void**)&w2T, g_w2T);

    // dynamic smem: 4 stages * (BM + BN) rows * 20 floats * 4B
    const int SM_BIG = 4*(128+128)*20*4;   // 81920
    const int SM_PV  = 4*(128+ 64)*20*4;   // 61440
    cudaFuncSetAttribute((const void*)mma_gemm<128,128,64,32,0>, cudaFuncAttributeMaxDynamicSharedMemorySize, SM_BIG);
    cudaFuncSetAttribute((const void*)mma_gemm<128,128,64,32,1>, cudaFuncAttributeMaxDynamicSharedMemorySize, SM_BIG);
    cudaFuncSetAttribute((const void*)mma_gemm<128,128,64,32,2>, cudaFuncAttributeMaxDynamicSharedMemorySize, SM_BIG);
    cudaFuncSetAttribute((const void*)mma_gemm<128, 64,32,32,0>, cudaFuncAttributeMaxDynamicSharedMemorySize, SM_PV);

    dim3 tb(32, 8);
    // 0) transpose weights into [N,K]
    transpose_k<<<dim3(DD/32, DD/32),  tb>>>(Wq, wqT, DD, DD);
    transpose_k<<<dim3(DD/32, DD/32),  tb>>>(Wk, wkT, DD, DD);
    transpose_k<<<dim3(DD/32, DD/32),  tb>>>(Wv, wvT, DD, DD);
    transpose_k<<<dim3(DD/32, DD/32),  tb>>>(Wo, woT, DD, DD);
    transpose_k<<<dim3(DFF/32, DD/32), tb>>>(W1, w1T, DD, DFF);
    transpose_k<<<dim3(DD/32, DFF/32), tb>>>(W2, w2T, DFF, DD);

    // 1) QKV projections: [8192,768] @ [768,768]^T(+b)
    mma_gemm<128,128,64,32,1><<<dim3(DD/128, MROWS/128, 1), 256, SM_BIG>>>(
        Q, wqT, q, bq, DD, DD, DD, DD, 1.f, 1, 0,0,0, 0,0,0, 0LL, 0LL);
    mma_gemm<128,128,64,32,1><<<dim3(DD/128, MROWS/128, 1), 256, SM_BIG>>>(
        K, wkT, k, bk, DD, DD, DD, DD, 1.f, 1, 0,0,0, 0,0,0, 0LL, 0LL);
    mma_gemm<128,128,64,32,1><<<dim3(DD/128, MROWS/128, 1), 256, SM_BIG>>>(
        V, wvT, v, bv, DD, DD, DD, DD, 1.f, 1, 0,0,0, 0,0,0, 0LL, 0LL);

    // 1b) v -> vT [b,h,dh,s]
    vtrans_k<<<dim3(SS/32, DHD/32, BB*HH), tb>>>(v, vT);

    // 2) scores = 0.125 * q @ k^T per (b,h): K=64
    mma_gemm<128,128,64,32,0><<<dim3(SS/128, SS/128, BB*HH), 256, SM_BIG>>>(
        q, k, sc, nullptr, DHD, DD, DD, SS, 0.125f, HH,
        DHD, SS, 0,                 // A: col off h*64, row off b*2048
        DHD, SS, 0,                 // B: same
        (long long)HH*SS*SS, (long long)SS*SS);

    // 3) softmax rows
    softmax_k<<<BB*HH*SS, 256>>>(sc);

    // 4) ctx = attn @ vT^T per (b,h): M=2048,N=64,K=2048
    mma_gemm<128,64,32,32,0><<<dim3(1, SS/128, BB*HH), 256, SM_PV>>>(
        sc, vT, ctx, nullptr, SS, SS, SS, DD, 1.f, HH,
        0, HH*SS, SS,               // A rows: (b*12+h)*2048
        0, HH*DHD, DHD,             // B rows: (b*12+h)*64
        (long long)SS*DD, (long long)DHD);

    // 5) attn_out = ctx @ Wo^T + bo
    mma_gemm<128,128,64,32,1><<<dim3(DD/128, MROWS/128, 1), 256, SM_BIG>>>(
        ctx, woT, tmp, bo, DD, DD, DD, DD, 1.f, 1, 0,0,0, 0,0,0, 0LL, 0LL);

    // 6) h = LN(Q + attn_out)
    add_ln_k<<<MROWS, 256>>>(tmp, Q, lng, lnb, h);

    // 7) ff1 = gelu(h @ W1^T + b1)
    mma_gemm<128,128,64,32,2><<<dim3(DFF/128, MROWS/128, 1), 256, SM_BIG>>>(
        h, w1T, ff1, b1, DD, DD, DD, DFF, 1.f, 1, 0,0,0, 0,0,0, 0LL, 0LL);

    // 8) out = ff1 @ W2^T + b2
    mma_gemm<128,128,64,32,1><<<dim3(DD/128, MROWS/128, 1), 256, SM_BIG>>>(
        ff1, w2T, out, b2, DFF, DFF, DFF, DD, 1.f, 1, 0,0,0, 0,0,0, 0LL, 0LL);
}

// round 4
// speedup vs baseline: 2.9327x; 1.2006x over previous
#include <cuda_runtime.h>
#include <math.h>
#include <stdint.h>

// Problem constants
#define BB   4
#define SS   2048
#define DD   768
#define HH   12
#define DHD  64
#define DFF  3072
#define MROWS (BB*SS)          // 8192

// -------- scratch (device globals; no allocations allowed) --------
static __device__ __align__(16) float g_q  [(size_t)BB*SS*DD];
static __device__ __align__(16) float g_k  [(size_t)BB*SS*DD];
static __device__ __align__(16) float g_v  [(size_t)BB*SS*DD];
static __device__ __align__(16) float g_vT [(size_t)BB*HH*DHD*SS];
static __device__ __align__(16) float g_ctx[(size_t)BB*SS*DD];
static __device__ __align__(16) float g_tmp[(size_t)BB*SS*DD];
static __device__ __align__(16) float g_h  [(size_t)BB*SS*DD];
static __device__ __align__(16) float g_ff1[(size_t)MROWS*DFF];
static __device__ __align__(16) float g_wqT[(size_t)DD*DD];
static __device__ __align__(16) float g_wkT[(size_t)DD*DD];
static __device__ __align__(16) float g_wvT[(size_t)DD*DD];
static __device__ __align__(16) float g_woT[(size_t)DD*DD];
static __device__ __align__(16) float g_w1T[(size_t)DFF*DD];
static __device__ __align__(16) float g_w2T[(size_t)DD*DFF];

__device__ __forceinline__ float gelu_exact(float x) {
    return 0.5f * x * (1.0f + erff(x * 0.7071067811865476f));
}

// ---------------- mma.sync tf32 helpers ----------------
__device__ __forceinline__ uint32_t f2tf(float x) {
    uint32_t u = __float_as_uint(x);
    asm("cvt.rna.tf32.f32 %0, %0;" : "+r"(u));
    return u;
}
__device__ __forceinline__ void mma8(float* c, const uint32_t* a, const uint32_t* b) {
    asm volatile("mma.sync.aligned.m16n8k8.row.col.f32.tf32.tf32.f32 "
        "{%0,%1,%2,%3}, {%4,%5,%6,%7}, {%8,%9}, {%0,%1,%2,%3};"
        : "+f"(c[0]), "+f"(c[1]), "+f"(c[2]), "+f"(c[3])
        : "r"(a[0]), "r"(a[1]), "r"(a[2]), "r"(a[3]), "r"(b[0]), "r"(b[1]));
}
template<int N> __device__ __forceinline__ void cp_wait() {
    asm volatile("cp.async.wait_group %0;" :: "n"(N));
}
#define CP_COMMIT() asm volatile("cp.async.commit_group;")
__device__ __forceinline__ void cp16(void* smem_dst, const void* gsrc) {
    uint32_t d = (uint32_t)__cvta_generic_to_shared(smem_dst);
    asm volatile("cp.async.cg.shared.global [%0], [%1], 16;" :: "r"(d), "l"(gsrc));
}

// =================== fused flash attention (tf32 mma) ===================
// grid: (SS/128, BB*HH). 256 threads = 8 warps, each warp owns 16 q-rows.
// q,k: [b*2048+s][h*64+dh]; vT: [(b*12+h)*64+dh][s]; ctx: [b*2048+s][768]
#define FA_PITCH 68

__global__ __launch_bounds__(256, 1)
void flash_k(const float* __restrict__ qg, const float* __restrict__ kg,
             const float* __restrict__ vtg, float* __restrict__ ctx)
{
    constexpr int P = FA_PITCH;
    extern __shared__ float sm[];
    float* Qs = sm;                          // [128][P], reused as P-buffer
    float* Ks = sm + 128*P;                  // [2][64][P]
    float* Vs = Ks + 2*64*P;                 // [2][64][P]

    const int tid = threadIdx.x, wid = tid >> 5, lane = tid & 31;
    const int qr = lane >> 2, qc = lane & 3;
    const int bh = blockIdx.y;
    const int bb = bh / HH, hh = bh % HH;
    const int q0 = blockIdx.x * 128;

    const float* Qg = qg  + (size_t)(bb*SS + q0)*DD + hh*DHD;
    const float* Kg = kg  + (size_t)(bb*SS)*DD + hh*DHD;
    const float* Vg = vtg + (size_t)bh*DHD*SS;

    // stage Q tile: 128 x 64 floats = 2048 16B-chunks, 8 per thread
    #pragma unroll
    for (int l = 0; l < 8; l++) {
        int ci = tid + l*256;
        int r = ci >> 4, c = ci & 15;
        cp16(Qs + r*P + c*4, Qg + (size_t)r*DD + c*4);
    }
    CP_COMMIT();
    // prefetch K/V tile 0
    {
        #pragma unroll
        for (int l = 0; l < 4; l++) {
            int ci = tid + l*256;
            int r = ci >> 4, c = ci & 15;
            cp16(Ks + r*P + c*4, Kg + (size_t)r*DD + c*4);
            cp16(Vs + r*P + c*4, Vg + (size_t)r*SS + c*4);
        }
    }
    CP_COMMIT();

    cp_wait<1>();          // Q done
    __syncthreads();

    // Q fragments (kept in registers for the whole kernel)
    uint32_t qf[8][4];
    {
        const float* Qr = Qs + (size_t)(wid*16 + qr)*P + qc;
        #pragma unroll
        for (int ks = 0; ks < 8; ks++) {
            qf[ks][0] = f2tf(Qr[ks*8]);
            qf[ks][1] = f2tf(Qr[8*P + ks*8]);
            qf[ks][2] = f2tf(Qr[ks*8 + 4]);
            qf[ks][3] = f2tf(Qr[8*P + ks*8 + 4]);
        }
    }

    float m0v = -3.4e38f, m1v = -3.4e38f, l0 = 0.f, l1 = 0.f;
    float o[8][4];
    #pragma unroll
    for (int nt = 0; nt < 8; nt++)
        #pragma unroll
        for (int e = 0; e < 4; e++) o[nt][e] = 0.f;

    const int NJ = SS / 64;   // 32
    for (int j = 0; j < NJ; j++) {
        cp_wait<0>();
        __syncthreads();
        // prefetch next K/V tile (overlaps with compute below)
        if (j + 1 < NJ) {
            float* Kn = Ks + ((j+1)&1)*64*P;
            float* Vn = Vs + ((j+1)&1)*64*P;
            const float* Kgn = Kg + (size_t)(j+1)*64*DD;
            const float* Vgn = Vg + (j+1)*64;
            #pragma unroll
            for (int l = 0; l < 4; l++) {
                int ci = tid + l*256;
                int r = ci >> 4, c = ci & 15;
                cp16(Kn + r*P + c*4, Kgn + (size_t)r*DD + c*4);
                cp16(Vn + r*P + c*4, Vgn + (size_t)r*SS + c*4);
            }
        }
        CP_COMMIT();

        const float* Kb = Ks + (j&1)*64*P;
        const float* Vb = Vs + (j&1)*64*P;

        // ---- S = Q @ K^T ----
        float s[8][4];
        #pragma unroll
        for (int nt = 0; nt < 8; nt++)
            #pragma unroll
            for (int e = 0; e < 4; e++) s[nt][e] = 0.f;
        #pragma unroll
        for (int ks = 0; ks < 8; ks++) {
            uint32_t kf[8][2];
            #pragma unroll
            for (int nt = 0; nt < 8; nt++) {
                const float* p = Kb + (size_t)(nt*8 + qr)*P + ks*8 + qc;
                kf[nt][0] = f2tf(p[0]);
                kf[nt][1] = f2tf(p[4]);
            }
            #pragma unroll
            for (int nt = 0; nt < 8; nt++)
                mma8(s[nt], qf[ks], kf[nt]);
        }

        // ---- online softmax ----
        float mx0 = -3.4e38f, mx1 = -3.4e38f;
        #pragma unroll
        for (int nt = 0; nt < 8; nt++) {
            #pragma unroll
            for (int e = 0; e < 4; e++) s[nt][e] *= 0.125f;
            mx0 = fmaxf(mx0, fmaxf(s[nt][0], s[nt][1]));
            mx1 = fmaxf(mx1, fmaxf(s[nt][2], s[nt][3]));
        }
        #pragma unroll
        for (int off = 1; off <= 2; off <<= 1) {
            mx0 = fmaxf(mx0, __shfl_xor_sync(0xffffffffu, mx0, off));
            mx1 = fmaxf(mx1, __shfl_xor_sync(0xffffffffu, mx1, off));
        }
        float mn0 = fmaxf(m0v, mx0), mn1 = fmaxf(m1v, mx1);
        float a0 = __expf(m0v - mn0), a1 = __expf(m1v - mn1);
        m0v = mn0; m1v = mn1;
        float sum0 = 0.f, sum1 = 0.f;
        #pragma unroll
        for (int nt = 0; nt < 8; nt++) {
            s[nt][0] = __expf(s[nt][0] - mn0); sum0 += s[nt][0];
            s[nt][1] = __expf(s[nt][1] - mn0); sum0 += s[nt][1];
            s[nt][2] = __expf(s[nt][2] - mn1); sum1 += s[nt][2];
            s[nt][3] = __expf(s[nt][3] - mn1); sum1 += s[nt][3];
        }
        #pragma unroll
        for (int off = 1; off <= 2; off <<= 1) {
            sum0 += __shfl_xor_sync(0xffffffffu, sum0, off);
            sum1 += __shfl_xor_sync(0xffffffffu, sum1, off);
        }
        l0 = l0*a0 + sum0;
        l1 = l1*a1 + sum1;
        #pragma unroll
        for (int nt = 0; nt < 8; nt++) {
            o[nt][0] *= a0; o[nt][1] *= a0;
            o[nt][2] *= a1; o[nt][3] *= a1;
        }

        // ---- P -> smem (own rows only), re-fragment as A ----
        float* Pw = Qs + (size_t)(wid*16)*P;
        __syncwarp();
        #pragma unroll
        for (int nt = 0; nt < 8; nt++) {
            *reinterpret_cast<float2*>(Pw + (size_t)qr*P     + nt*8 + 2*qc) = make_float2(s[nt][0], s[nt][1]);
            *reinterpret_cast<float2*>(Pw + (size_t)(qr+8)*P + nt*8 + 2*qc) = make_float2(s[nt][2], s[nt][3]);
        }
        __syncwarp();

        // ---- O += P @ V ----
        #pragma unroll
        for (int ks = 0; ks < 8; ks++) {
            uint32_t af[4];
            const float* pp = Pw + (size_t)qr*P + ks*8 + qc;
            af[0] = f2tf(pp[0]);
            af[1] = f2tf(pp[8*P]);
            af[2] = f2tf(pp[4]);
            af[3] = f2tf(pp[8*P + 4]);
            #pragma unroll
            for (int nt = 0; nt < 8; nt++) {
                const float* vp = Vb + (size_t)(nt*8 + qr)*P + ks*8 + qc;
                uint32_t bf[2] = { f2tf(vp[0]), f2tf(vp[4]) };
                mma8(o[nt], af, bf);
            }
        }
        __syncwarp();
    }

    // ---- epilogue: O /= l, write ctx ----
    float inv0 = 1.f / l0, inv1 = 1.f / l1;
    const int r0 = q0 + wid*16 + qr;
    float* C0 = ctx + (size_t)(bb*SS + r0)*DD + hh*DHD + 2*qc;
    float* C1 = C0 + 8*DD;
    #pragma unroll
    for (int nt = 0; nt < 8; nt++) {
        *reinterpret_cast<float2*>(C0 + nt*8) = make_float2(o[nt][0]*inv0, o[nt][1]*inv0);
        *reinterpret_cast<float2*>(C1 + nt*8) = make_float2(o[nt][2]*inv1, o[nt][3]*inv1);
    }
}

// stage loader: A tile [BM x 16], B tile [BN x 16], both K-contiguous rows
template<int BM, int BN>
__device__ __forceinline__ void load_tiles(float* sA, float* sB,
    const float* __restrict__ Ab, const float* __restrict__ Bb,
    int lda, int ldb, int kt, int st, int tid)
{
    constexpr int PITCH = 20;
    constexpr int ACH = (BM*4)/256;
    constexpr int BCH = (BN*4)/256;
    float* dA = sA + (size_t)st*BM*PITCH;
    #pragma unroll
    for (int l = 0; l < ACH; l++) {
        int ci = tid + l*256;
        int r = ci >> 2, c = ci & 3;
        cp16(dA + r*PITCH + c*4, Ab + (size_t)r*lda + kt*16 + c*4);
    }
    float* dB = sB + (size_t)st*BN*PITCH;
    #pragma unroll
    for (int l = 0; l < BCH; l++) {
        int ci = tid + l*256;
        int r = ci >> 2, c = ci & 3;
        cp16(dB + r*PITCH + c*4, Bb + (size_t)r*ldb + kt*16 + c*4);
    }
}

// =================== tf32 mma.sync GEMM ===================
// C[M,N] = alpha * A[M,K] @ B[N,K]^T (+bias)(+gelu).
template<int BM, int BN, int WM, int WN, int EPI>
__global__ __launch_bounds__(256, 2)
void mma_gemm(const float* __restrict__ A, const float* __restrict__ Bm,
              float* __restrict__ C, const float* __restrict__ bias,
              int K, int lda, int ldb, int ldc, float alpha)
{
    constexpr int S = 4;
    constexpr int PITCH = 20;
    constexpr int WARPS_N = BN/WN;
    constexpr int MT = WM/16, NT = WN/8;

    extern __shared__ float sm[];
    float* sA = sm;
    float* sB = sm + (size_t)S*BM*PITCH;

    const int tid = threadIdx.x;
    const int m0 = blockIdx.y * BM, n0 = blockIdx.x * BN;

    const float* Ab = A  + (size_t)m0*lda;
    const float* Bb = Bm + (size_t)n0*ldb;

    const int KT = K / 16;

    #pragma unroll
    for (int s = 0; s < S-1; s++) {
        if (s < KT) load_tiles<BM,BN>(sA, sB, Ab, Bb, lda, ldb, s, s, tid);
        CP_COMMIT();
    }

    const int wid = tid >> 5, lane = tid & 31;
    const int wm = (wid / WARPS_N) * WM;
    const int wn = (wid % WARPS_N) * WN;
    const int qr = lane >> 2, qc = lane & 3;

    float acc[MT][NT][4];
    #pragma unroll
    for (int i = 0; i < MT; i++)
        #pragma unroll
        for (int j = 0; j < NT; j++)
            #pragma unroll
            for (int e = 0; e < 4; e++) acc[i][j][e] = 0.f;

    for (int kt = 0; kt < KT; kt++) {
        cp_wait<S-2>();
        __syncthreads();
        const int nk = kt + S - 1;
        if (nk < KT) load_tiles<BM,BN>(sA, sB, Ab, Bb, lda, ldb, nk, nk % S, tid);
        CP_COMMIT();

        const float* As = sA + (size_t)(kt % S)*BM*PITCH;
        const float* Bs = sB + (size_t)(kt % S)*BN*PITCH;
        #pragma unroll
        for (int ks = 0; ks < 2; ks++) {
            uint32_t af[MT][4], bf[NT][2];
            #pragma unroll
            for (int mt = 0; mt < MT; mt++) {
                const float* p = As + (size_t)(wm + mt*16 + qr)*PITCH + ks*8 + qc;
                af[mt][0] = f2tf(p[0]);
                af[mt][1] = f2tf(p[8*PITCH]);
                af[mt][2] = f2tf(p[4]);
                af[mt][3] = f2tf(p[8*PITCH + 4]);
            }
            #pragma unroll
            for (int nt = 0; nt < NT; nt++) {
                const float* p = Bs + (size_t)(wn + nt*8 + qr)*PITCH + ks*8 + qc;
                bf[nt][0] = f2tf(p[0]);
                bf[nt][1] = f2tf(p[4]);
            }
            #pragma unroll
            for (int mt = 0; mt < MT; mt++)
                #pragma unroll
                for (int nt = 0; nt < NT; nt++)
                    mma8(acc[mt][nt], af[mt], bf[nt]);
        }
    }

    // ---- epilogue ----
    #pragma unroll
    for (int mt = 0; mt < MT; mt++) {
        #pragma unroll
        for (int nt = 0; nt < NT; nt++) {
            const int cc = n0 + wn + nt*8 + qc*2;
            float b0 = 0.f, b1 = 0.f;
            if (EPI >= 1) { b0 = __ldg(&bias[cc]); b1 = __ldg(&bias[cc+1]); }
            float x0 = acc[mt][nt][0]*alpha + b0;
            float x1 = acc[mt][nt][1]*alpha + b1;
            float x2 = acc[mt][nt][2]*alpha + b0;
            float x3 = acc[mt][nt][3]*alpha + b1;
            if (EPI == 2) {
                x0 = gelu_exact(x0); x1 = gelu_exact(x1);
                x2 = gelu_exact(x2); x3 = gelu_exact(x3);
            }
            const size_t r0 = (size_t)(m0 + wm + mt*16 + qr);
            *reinterpret_cast<float2*>(C + r0*ldc + cc)     = make_float2(x0, x1);
            *reinterpret_cast<float2*>(C + (r0+8)*ldc + cc) = make_float2(x2, x3);
        }
    }
}

// =================== transposes ===================
__global__ __launch_bounds__(256) void transpose_k(const float* __restrict__ src,
                                                   float* __restrict__ dst, int R, int C)
{
    __shared__ float tile[32][33];
    const int c0 = blockIdx.x*32, r0 = blockIdx.y*32;
    const int x = threadIdx.x, y = threadIdx.y;
    #pragma unroll
    for (int i = 0; i < 32; i += 8) tile[y+i][x] = src[(size_t)(r0+y+i)*C + c0+x];
    __syncthreads();
    #pragma unroll
    for (int i = 0; i < 32; i += 8) dst[(size_t)(c0+y+i)*R + r0+x] = tile[x][y+i];
}

// v [b*2048+s][h*64+d] -> vT [(b*12+h)*64+d][s]
__global__ __launch_bounds__(256) void vtrans_k(const float* __restrict__ v,
                                                float* __restrict__ vt)
{
    __shared__ float tile[32][33];
    const int z = blockIdx.z, bb = z/HH, hh = z%HH;
    const int s0 = blockIdx.x*32, d0 = blockIdx.y*32;
    const int x = threadIdx.x, y = threadIdx.y;
    #pragma unroll
    for (int i = 0; i < 32; i += 8)
        tile[y+i][x] = v[(size_t)(bb*SS + s0 + y+i)*DD + hh*DHD + d0 + x];
    __syncthreads();
    #pragma unroll
    for (int i = 0; i < 32; i += 8)
        vt[(size_t)(z*DHD + d0 + y+i)*SS + s0 + x] = tile[x][y+i];
}

// =================== block reduce / LN ===================
__device__ __forceinline__ float block_reduce(float val, bool ismax) {
    __shared__ float sh[32];
    int lane = threadIdx.x & 31, w = threadIdx.x >> 5;
    #pragma unroll
    for (int off=16; off>0; off>>=1) {
        float o = __shfl_xor_sync(0xffffffffu, val, off);
        val = ismax ? fmaxf(val, o) : (val + o);
    }
    if (lane == 0) sh[w] = val;
    __syncthreads();
    int nw = blockDim.x >> 5;
    if (w == 0) {
        float v = (lane < nw) ? sh[lane] : (ismax ? -3.4e38f : 0.f);
        #pragma unroll
        for (int off=16; off>0; off>>=1) {
            float o = __shfl_xor_sync(0xffffffffu, v, off);
            v = ismax ? fmaxf(v, o) : (v + o);
        }
        if (lane == 0) sh[0] = v;
    }
    __syncthreads();
    float r = sh[0];
    __syncthreads();
    return r;
}

__global__ __launch_bounds__(256) void add_ln_k(
    const float* __restrict__ x, const float* __restrict__ res,
    const float* __restrict__ g, const float* __restrict__ b,
    float* __restrict__ y)
{
    size_t base = (size_t)blockIdx.x * DD;
    int t = threadIdx.x;
    float v[3];
    float s = 0.f;
    #pragma unroll
    for (int i=0;i<3;i++){
        int c = t + i*256;
        v[i] = x[base + c] + res[base + c];
        s += v[i];
    }
    s = block_reduce(s, false);
    float mu = s * (1.0f/DD);
    float q = 0.f;
    #pragma unroll
    for (int i=0;i<3;i++){ float d = v[i]-mu; q += d*d; }
    q = block_reduce(q, false);
    float rstd = rsqrtf(q * (1.0f/DD) + 1e-5f);
    #pragma unroll
    for (int i=0;i<3;i++){
        int c = t + i*256;
        y[base + c] = (v[i]-mu)*rstd*g[c] + b[c];
    }
}

// =================== launch ===================
extern "C" void kernel_launch(void* const* d_in, const int* in_sizes, int n_in,
                              void* d_out, int out_size)
{
    const float* Q   = (const float*)d_in[0];
    const float* K   = (const float*)d_in[1];
    const float* V   = (const float*)d_in[2];
    const float* Wq  = (const float*)d_in[3];
    const float* bq  = (const float*)d_in[4];
    const float* Wk  = (const float*)d_in[5];
    const float* bk  = (const float*)d_in[6];
    const float* Wv  = (const float*)d_in[7];
    const float* bv  = (const float*)d_in[8];
    const float* Wo  = (const float*)d_in[9];
    const float* bo  = (const float*)d_in[10];
    const float* lng = (const float*)d_in[11];
    const float* lnb = (const float*)d_in[12];
    const float* W1  = (const float*)d_in[13];
    const float* b1  = (const float*)d_in[14];
    const float* W2  = (const float*)d_in[15];
    const float* b2  = (const float*)d_in[16];
    float* out = (float*)d_out;

    float *q,*k,*v,*vT,*ctx,*tmp,*h,*ff1,*wqT,*wkT,*wvT,*woT,*w1T,*w2T;
    cudaGetSymbolAddress((void**)&q,   g_q);
    cudaGetSymbolAddress((void**)&k,   g_k);
    cudaGetSymbolAddress((void**)&v,   g_v);
    cudaGetSymbolAddress((void**)&vT,  g_vT);
    cudaGetSymbolAddress((void**)&ctx, g_ctx);
    cudaGetSymbolAddress((void**)&tmp, g_tmp);
    cudaGetSymbolAddress((void**)&h,   g_h);
    cudaGetSymbolAddress((void**)&ff1, g_ff1);
    cudaGetSymbolAddress((void**)&wqT, g_wqT);
    cudaGetSymbolAddress((void**)&wkT, g_wkT);
    cudaGetSymbolAddress((void**)&wvT, g_wvT);
    cudaGetSymbolAddress((void**)&woT, g_woT);
    cudaGetSymbolAddress((void**)&w1T, g_w1T);
    cudaGetSymbolAddress((void**)&w2T, g_w2T);

    const int SM_BIG   = 4*(128+128)*20*4;                    // 81920
    const int SM_FLASH = (128*FA_PITCH + 4*64*FA_PITCH)*4;    // 104448
    cudaFuncSetAttribute((const void*)mma_gemm<128,128,64,32,1>, cudaFuncAttributeMaxDynamicSharedMemorySize, SM_BIG);
    cudaFuncSetAttribute((const void*)mma_gemm<128,128,64,32,2>, cudaFuncAttributeMaxDynamicSharedMemorySize, SM_BIG);
    cudaFuncSetAttribute((const void*)flash_k, cudaFuncAttributeMaxDynamicSharedMemorySize, SM_FLASH);

    dim3 tb(32, 8);
    // 0) transpose weights into [N,K]
    transpose_k<<<dim3(DD/32, DD/32),  tb>>>(Wq, wqT, DD, DD);
    transpose_k<<<dim3(DD/32, DD/32),  tb>>>(Wk, wkT, DD, DD);
    transpose_k<<<dim3(DD/32, DD/32),  tb>>>(Wv, wvT, DD, DD);
    transpose_k<<<dim3(DD/32, DD/32),  tb>>>(Wo, woT, DD, DD);
    transpose_k<<<dim3(DFF/32, DD/32), tb>>>(W1, w1T, DD, DFF);
    transpose_k<<<dim3(DD/32, DFF/32), tb>>>(W2, w2T, DFF, DD);

    // 1) QKV projections
    mma_gemm<128,128,64,32,1><<<dim3(DD/128, MROWS/128), 256, SM_BIG>>>(
        Q, wqT, q, bq, DD, DD, DD, DD, 1.f);
    mma_gemm<128,128,64,32,1><<<dim3(DD/128, MROWS/128), 256, SM_BIG>>>(
        K, wkT, k, bk, DD, DD, DD, DD, 1.f);
    mma_gemm<128,128,64,32,1><<<dim3(DD/128, MROWS/128), 256, SM_BIG>>>(
        V, wvT, v, bv, DD, DD, DD, DD, 1.f);

    // 1b) v -> vT [b,h,dh,s]
    vtrans_k<<<dim3(SS/32, DHD/32, BB*HH), tb>>>(v, vT);

    // 2-4) fused flash attention -> ctx
    flash_k<<<dim3(SS/128, BB*HH), 256, SM_FLASH>>>(q, k, vT, ctx);

    // 5) attn_out = ctx @ Wo^T + bo
    mma_gemm<128,128,64,32,1><<<dim3(DD/128, MROWS/128), 256, SM_BIG>>>(
        ctx, woT, tmp, bo, DD, DD, DD, DD, 1.f);

    // 6) h = LN(Q + attn_out)
    add_ln_k<<<MROWS, 256>>>(tmp, Q, lng, lnb, h);

    // 7) ff1 = gelu(h @ W1^T + b1)
    mma_gemm<128,128,64,32,2><<<dim3(DFF/128, MROWS/128), 256, SM_BIG>>>(
        h, w1T, ff1, b1, DD, DD, DD, DFF, 1.f);

    // 8) out = ff1 @ W2^T + b2
    mma_gemm<128,128,64,32,1><<<dim3(DD/128, MROWS/128), 256, SM_BIG>>>(
        ff1, w2T, out, b2, DFF, DFF, DFF, DD, 1.f);
}

// round 6
// speedup vs baseline: 4.2964x; 1.4650x over previous
#include <cuda_runtime.h>
#include <cuda_bf16.h>
#include <math.h>
#include <stdint.h>

// Problem constants
#define BB   4
#define SS   2048
#define DD   768
#define HH   12
#define DHD  64
#define DFF  3072
#define MROWS (BB*SS)          // 8192

// -------- scratch (device globals; no allocations allowed) --------
static __device__ __align__(16) __nv_bfloat16 g_xq [(size_t)BB*SS*DD];   // bf16 copies of inputs
static __device__ __align__(16) __nv_bfloat16 g_xk [(size_t)BB*SS*DD];
static __device__ __align__(16) __nv_bfloat16 g_xv [(size_t)BB*SS*DD];
static __device__ __align__(16) __nv_bfloat16 g_qb [(size_t)BB*SS*DD];
static __device__ __align__(16) __nv_bfloat16 g_kb [(size_t)BB*SS*DD];
static __device__ __align__(16) __nv_bfloat16 g_vb [(size_t)BB*SS*DD];
static __device__ __align__(16) __nv_bfloat16 g_vTb[(size_t)BB*HH*DHD*SS];
static __device__ __align__(16) __nv_bfloat16 g_ctxb[(size_t)BB*SS*DD];
static __device__ __align__(16) float g_tmp[(size_t)BB*SS*DD];
static __device__ __align__(16) float g_h  [(size_t)BB*SS*DD];
static __device__ __align__(16) float g_ff1[(size_t)MROWS*DFF];
static __device__ __align__(16) __nv_bfloat16 g_wqT[(size_t)DD*DD];
static __device__ __align__(16) __nv_bfloat16 g_wkT[(size_t)DD*DD];
static __device__ __align__(16) __nv_bfloat16 g_wvT[(size_t)DD*DD];
static __device__ __align__(16) __nv_bfloat16 g_woT[(size_t)DD*DD];
static __device__ __align__(16) float g_w1T[(size_t)DFF*DD];
static __device__ __align__(16) float g_w2T[(size_t)DD*DFF];

__device__ __forceinline__ float gelu_exact(float x) {
    return 0.5f * x * (1.0f + erff(x * 0.7071067811865476f));
}

// ---------------- helpers ----------------
__device__ __forceinline__ uint32_t f2tf(float x) {
    uint32_t u = __float_as_uint(x);
    asm("cvt.rna.tf32.f32 %0, %0;" : "+r"(u));
    return u;
}
__device__ __forceinline__ float tf32r(float x) { return __uint_as_float(f2tf(x)); }
__device__ __forceinline__ uint32_t pack_bf16(float lo, float hi) {
    uint32_t r;
    asm("cvt.rn.bf16x2.f32 %0, %1, %2;" : "=r"(r) : "f"(hi), "f"(lo));
    return r;
}
__device__ __forceinline__ uint32_t ldb32(const __nv_bfloat16* p) {
    return *reinterpret_cast<const uint32_t*>(p);
}
__device__ __forceinline__ void mma_tf(float* c, const uint32_t* a, const uint32_t* b) {
    asm volatile("mma.sync.aligned.m16n8k8.row.col.f32.tf32.tf32.f32 "
        "{%0,%1,%2,%3}, {%4,%5,%6,%7}, {%8,%9}, {%0,%1,%2,%3};"
        : "+f"(c[0]), "+f"(c[1]), "+f"(c[2]), "+f"(c[3])
        : "r"(a[0]), "r"(a[1]), "r"(a[2]), "r"(a[3]), "r"(b[0]), "r"(b[1]));
}
__device__ __forceinline__ void mma_bf(float* c, const uint32_t* a, const uint32_t* b) {
    asm volatile("mma.sync.aligned.m16n8k16.row.col.f32.bf16.bf16.f32 "
        "{%0,%1,%2,%3}, {%4,%5,%6,%7}, {%8,%9}, {%0,%1,%2,%3};"
        : "+f"(c[0]), "+f"(c[1]), "+f"(c[2]), "+f"(c[3])
        : "r"(a[0]), "r"(a[1]), "r"(a[2]), "r"(a[3]), "r"(b[0]), "r"(b[1]));
}
template<int N> __device__ __forceinline__ void cp_wait() {
    asm volatile("cp.async.wait_group %0;" :: "n"(N));
}
#define CP_COMMIT() asm volatile("cp.async.commit_group;")
__device__ __forceinline__ void cp16(void* smem_dst, const void* gsrc) {
    uint32_t d = (uint32_t)__cvta_generic_to_shared(smem_dst);
    asm volatile("cp.async.cg.shared.global [%0], [%1], 16;" :: "r"(d), "l"(gsrc));
}

// =================== fp32 -> bf16 copy ===================
__global__ __launch_bounds__(256) void f2b_k(const float* __restrict__ x,
                                             __nv_bfloat16* __restrict__ y)
{
    size_t i = ((size_t)blockIdx.x*256 + threadIdx.x) * 4;
    float4 v = *reinterpret_cast<const float4*>(x + i);
    uint2 o;
    o.x = pack_bf16(v.x, v.y);
    o.y = pack_bf16(v.z, v.w);
    *reinterpret_cast<uint2*>(y + i) = o;
}

// =================== transposes ===================
// MODE 0: out bf16; MODE 1: out fp32 pre-rounded to tf32
template<int MODE>
__global__ __launch_bounds__(256) void transpose_t(const float* __restrict__ src,
                                                   void* __restrict__ dst, int R, int C)
{
    __shared__ float tile[32][33];
    const int c0 = blockIdx.x*32, r0 = blockIdx.y*32;
    const int x = threadIdx.x, y = threadIdx.y;
    #pragma unroll
    for (int i = 0; i < 32; i += 8) tile[y+i][x] = src[(size_t)(r0+y+i)*C + c0+x];
    __syncthreads();
    if (MODE == 0) {
        __nv_bfloat16* d = (__nv_bfloat16*)dst;
        #pragma unroll
        for (int i = 0; i < 32; i += 8)
            d[(size_t)(c0+y+i)*R + r0+x] = __float2bfloat16_rn(tile[x][y+i]);
    } else {
        float* d = (float*)dst;
        #pragma unroll
        for (int i = 0; i < 32; i += 8)
            d[(size_t)(c0+y+i)*R + r0+x] = tf32r(tile[x][y+i]);
    }
}

// v bf16 [b*2048+s][h*64+d] -> vT bf16 [(b*12+h)*64+d][s]
__global__ __launch_bounds__(256) void vtrans_k(const __nv_bfloat16* __restrict__ v,
                                                __nv_bfloat16* __restrict__ vt)
{
    __shared__ __nv_bfloat16 tile[32][34];
    const int z = blockIdx.z, bb = z/HH, hh = z%HH;
    const int s0 = blockIdx.x*32, d0 = blockIdx.y*32;
    const int x = threadIdx.x, y = threadIdx.y;
    #pragma unroll
    for (int i = 0; i < 32; i += 8)
        tile[y+i][x] = v[(size_t)(bb*SS + s0 + y+i)*DD + hh*DHD + d0 + x];
    __syncthreads();
    #pragma unroll
    for (int i = 0; i < 32; i += 8)
        vt[(size_t)(z*DHD + d0 + y+i)*SS + s0 + x] = tile[x][y+i];
}

// =================== bf16 GEMM: C = A[M,K] @ B[N,K]^T + bias ===================
// A,B bf16. OUTBF=1 -> bf16 out, else fp32 out. BM=BN=128, BK=32, 8 warps 64x32.
template<int OUTBF>
__global__ __launch_bounds__(256, 2)
void bgemm(const __nv_bfloat16* __restrict__ A, const __nv_bfloat16* __restrict__ Bm,
           void* __restrict__ Cv, const float* __restrict__ bias,
           int K, int lda, int ldb, int ldc)
{
    constexpr int S = 3, PITCH = 40, BM = 128, BN = 128;
    extern __shared__ __nv_bfloat16 smb[];
    __nv_bfloat16* sA = smb;
    __nv_bfloat16* sB = smb + (size_t)S*BM*PITCH;

    const int tid = threadIdx.x;
    const int m0 = blockIdx.y * BM, n0 = blockIdx.x * BN;
    const __nv_bfloat16* Ab = A  + (size_t)m0*lda;
    const __nv_bfloat16* Bb = Bm + (size_t)n0*ldb;
    const int KT = K / 32;

    auto load_stage = [&](int kt, int st) {
        __nv_bfloat16* dA = sA + (size_t)st*BM*PITCH;
        __nv_bfloat16* dB = sB + (size_t)st*BN*PITCH;
        #pragma unroll
        for (int l = 0; l < 2; l++) {
            int ci = tid + l*256;
            int r = ci >> 2, c = ci & 3;
            cp16(dA + r*PITCH + c*8, Ab + (size_t)r*lda + kt*32 + c*8);
            cp16(dB + r*PITCH + c*8, Bb + (size_t)r*ldb + kt*32 + c*8);
        }
    };

    #pragma unroll
    for (int s = 0; s < S-1; s++) { load_stage(s, s); CP_COMMIT(); }

    const int wid = tid >> 5, lane = tid & 31;
    const int wm = (wid >> 2) * 64;      // 2 warp rows
    const int wn = (wid & 3) * 32;       // 4 warp cols
    const int qr = lane >> 2, qc = lane & 3;

    float acc[4][4][4];
    #pragma unroll
    for (int i=0;i<4;i++) for (int j=0;j<4;j++) for (int e=0;e<4;e++) acc[i][j][e]=0.f;

    for (int kt = 0; kt < KT; kt++) {
        cp_wait<1>();
        __syncthreads();
        const int nk = kt + S - 1;
        if (nk < KT) load_stage(nk, nk % S);
        CP_COMMIT();

        const __nv_bfloat16* As = sA + (size_t)(kt % S)*BM*PITCH;
        const __nv_bfloat16* Bs = sB + (size_t)(kt % S)*BN*PITCH;
        #pragma unroll
        for (int ks = 0; ks < 2; ks++) {
            uint32_t af[4][4], bf[4][2];
            #pragma unroll
            for (int mt = 0; mt < 4; mt++) {
                const __nv_bfloat16* p = As + (size_t)(wm + mt*16 + qr)*PITCH + ks*16 + 2*qc;
                af[mt][0] = ldb32(p);
                af[mt][1] = ldb32(p + 8*PITCH);
                af[mt][2] = ldb32(p + 8);
                af[mt][3] = ldb32(p + 8*PITCH + 8);
            }
            #pragma unroll
            for (int nt = 0; nt < 4; nt++) {
                const __nv_bfloat16* p = Bs + (size_t)(wn + nt*8 + qr)*PITCH + ks*16 + 2*qc;
                bf[nt][0] = ldb32(p);
                bf[nt][1] = ldb32(p + 8);
            }
            #pragma unroll
            for (int mt = 0; mt < 4; mt++)
                #pragma unroll
                for (int nt = 0; nt < 4; nt++)
                    mma_bf(acc[mt][nt], af[mt], bf[nt]);
        }
        __syncthreads();
    }

    #pragma unroll
    for (int mt = 0; mt < 4; mt++) {
        #pragma unroll
        for (int nt = 0; nt < 4; nt++) {
            const int cc = n0 + wn + nt*8 + qc*2;
            float b0 = __ldg(&bias[cc]), b1 = __ldg(&bias[cc+1]);
            float x0 = acc[mt][nt][0] + b0, x1 = acc[mt][nt][1] + b1;
            float x2 = acc[mt][nt][2] + b0, x3 = acc[mt][nt][3] + b1;
            const size_t r0 = (size_t)(m0 + wm + mt*16 + qr);
            if (OUTBF) {
                __nv_bfloat16* Cb = (__nv_bfloat16*)Cv;
                *reinterpret_cast<uint32_t*>(Cb + r0*ldc + cc)     = pack_bf16(x0, x1);
                *reinterpret_cast<uint32_t*>(Cb + (r0+8)*ldc + cc) = pack_bf16(x2, x3);
            } else {
                float* Cf = (float*)Cv;
                *reinterpret_cast<float2*>(Cf + r0*ldc + cc)     = make_float2(x0, x1);
                *reinterpret_cast<float2*>(Cf + (r0+8)*ldc + cc) = make_float2(x2, x3);
            }
        }
    }
}

// =================== fused flash attention (bf16 mma) ===================
// grid: (SS/128, BB*HH). 256 threads = 8 warps, each warp owns 16 q-rows.
#define QP 72

__global__ __launch_bounds__(256, 2)
void flash_k(const __nv_bfloat16* __restrict__ qg, const __nv_bfloat16* __restrict__ kg,
             const __nv_bfloat16* __restrict__ vtg, __nv_bfloat16* __restrict__ ctx)
{
    extern __shared__ __nv_bfloat16 smb[];
    __nv_bfloat16* Qs = smb;                 // [128][QP], reused as P buffer
    __nv_bfloat16* Ks = smb + 128*QP;        // [2][64][QP]
    __nv_bfloat16* Vs = Ks + 2*64*QP;        // [2][64][QP]

    const int tid = threadIdx.x, wid = tid >> 5, lane = tid & 31;
    const int qr = lane >> 2, qc = lane & 3;
    const int bh = blockIdx.y;
    const int bb = bh / HH, hh = bh % HH;
    const int q0 = blockIdx.x * 128;

    const __nv_bfloat16* Qg = qg  + (size_t)(bb*SS + q0)*DD + hh*DHD;
    const __nv_bfloat16* Kg = kg  + (size_t)(bb*SS)*DD + hh*DHD;
    const __nv_bfloat16* Vg = vtg + (size_t)bh*DHD*SS;

    // stage Q: 128 rows x 8 chunks (16B)
    #pragma unroll
    for (int l = 0; l < 4; l++) {
        int ci = tid + l*256;
        int r = ci >> 3, c = ci & 7;
        cp16(Qs + r*QP + c*8, Qg + (size_t)r*DD + c*8);
    }
    CP_COMMIT();
    // prefetch K/V tile 0: 64 rows x 8 chunks each
    #pragma unroll
    for (int l = 0; l < 2; l++) {
        int ci = tid + l*256;
        int r = ci >> 3, c = ci & 7;
        cp16(Ks + r*QP + c*8, Kg + (size_t)r*DD + c*8);
        cp16(Vs + r*QP + c*8, Vg + (size_t)r*SS + c*8);
    }
    CP_COMMIT();

    cp_wait<1>();
    __syncthreads();

    // Q fragments in registers: 4 ksteps of 16
    uint32_t qf[4][4];
    {
        const __nv_bfloat16* Qr = Qs + (size_t)(wid*16 + qr)*QP + 2*qc;
        #pragma unroll
        for (int ks = 0; ks < 4; ks++) {
            qf[ks][0] = ldb32(Qr + ks*16);
            qf[ks][1] = ldb32(Qr + 8*QP + ks*16);
            qf[ks][2] = ldb32(Qr + ks*16 + 8);
            qf[ks][3] = ldb32(Qr + 8*QP + ks*16 + 8);
        }
    }

    float m0v = -3.4e38f, m1v = -3.4e38f, l0 = 0.f, l1 = 0.f;
    float o[8][4];
    #pragma unroll
    for (int nt = 0; nt < 8; nt++)
        #pragma unroll
        for (int e = 0; e < 4; e++) o[nt][e] = 0.f;

    const int NJ = SS / 64;
    for (int j = 0; j < NJ; j++) {
        cp_wait<0>();
        __syncthreads();
        if (j + 1 < NJ) {
            __nv_bfloat16* Kn = Ks + ((j+1)&1)*64*QP;
            __nv_bfloat16* Vn = Vs + ((j+1)&1)*64*QP;
            const __nv_bfloat16* Kgn = Kg + (size_t)(j+1)*64*DD;
            const __nv_bfloat16* Vgn = Vg + (j+1)*64;
            #pragma unroll
            for (int l = 0; l < 2; l++) {
                int ci = tid + l*256;
                int r = ci >> 3, c = ci & 7;
                cp16(Kn + r*QP + c*8, Kgn + (size_t)r*DD + c*8);
                cp16(Vn + r*QP + c*8, Vgn + (size_t)r*SS + c*8);
            }
        }
        CP_COMMIT();

        const __nv_bfloat16* Kb = Ks + (j&1)*64*QP;
        const __nv_bfloat16* Vb = Vs + (j&1)*64*QP;

        // ---- S = Q @ K^T ----
        float s[8][4];
        #pragma unroll
        for (int nt = 0; nt < 8; nt++)
            #pragma unroll
            for (int e = 0; e < 4; e++) s[nt][e] = 0.f;
        #pragma unroll
        for (int ks = 0; ks < 4; ks++) {
            #pragma unroll
            for (int nt = 0; nt < 8; nt++) {
                const __nv_bfloat16* p = Kb + (size_t)(nt*8 + qr)*QP + ks*16 + 2*qc;
                uint32_t kf[2] = { ldb32(p), ldb32(p + 8) };
                mma_bf(s[nt], qf[ks], kf);
            }
        }

        // ---- online softmax ----
        float mx0 = -3.4e38f, mx1 = -3.4e38f;
        #pragma unroll
        for (int nt = 0; nt < 8; nt++) {
            #pragma unroll
            for (int e = 0; e < 4; e++) s[nt][e] *= 0.125f;
            mx0 = fmaxf(mx0, fmaxf(s[nt][0], s[nt][1]));
            mx1 = fmaxf(mx1, fmaxf(s[nt][2], s[nt][3]));
        }
        #pragma unroll
        for (int off = 1; off <= 2; off <<= 1) {
            mx0 = fmaxf(mx0, __shfl_xor_sync(0xffffffffu, mx0, off));
            mx1 = fmaxf(mx1, __shfl_xor_sync(0xffffffffu, mx1, off));
        }
        float mn0 = fmaxf(m0v, mx0), mn1 = fmaxf(m1v, mx1);
        float a0 = __expf(m0v - mn0), a1 = __expf(m1v - mn1);
        m0v = mn0; m1v = mn1;
        float sum0 = 0.f, sum1 = 0.f;
        #pragma unroll
        for (int nt = 0; nt < 8; nt++) {
            s[nt][0] = __expf(s[nt][0] - mn0); sum0 += s[nt][0];
            s[nt][1] = __expf(s[nt][1] - mn0); sum0 += s[nt][1];
            s[nt][2] = __expf(s[nt][2] - mn1); sum1 += s[nt][2];
            s[nt][3] = __expf(s[nt][3] - mn1); sum1 += s[nt][3];
        }
        #pragma unroll
        for (int off = 1; off <= 2; off <<= 1) {
            sum0 += __shfl_xor_sync(0xffffffffu, sum0, off);
            sum1 += __shfl_xor_sync(0xffffffffu, sum1, off);
        }
        l0 = l0*a0 + sum0;
        l1 = l1*a1 + sum1;
        #pragma unroll
        for (int nt = 0; nt < 8; nt++) {
            o[nt][0] *= a0; o[nt][1] *= a0;
            o[nt][2] *= a1; o[nt][3] *= a1;
        }

        // ---- P -> smem bf16 (warp-private region) ----
        __nv_bfloat16* Pw = Qs + (size_t)(wid*16)*QP;
        __syncwarp();
        #pragma unroll
        for (int nt = 0; nt < 8; nt++) {
            *reinterpret_cast<uint32_t*>(Pw + (size_t)qr*QP     + nt*8 + 2*qc) = pack_bf16(s[nt][0], s[nt][1]);
            *reinterpret_cast<uint32_t*>(Pw + (size_t)(qr+8)*QP + nt*8 + 2*qc) = pack_bf16(s[nt][2], s[nt][3]);
        }
        __syncwarp();

        // ---- O += P @ V ----
        #pragma unroll
        for (int ks = 0; ks < 4; ks++) {
            uint32_t af[4];
            const __nv_bfloat16* pp = Pw + (size_t)qr*QP + ks*16 + 2*qc;
            af[0] = ldb32(pp);
            af[1] = ldb32(pp + 8*QP);
            af[2] = ldb32(pp + 8);
            af[3] = ldb32(pp + 8*QP + 8);
            #pragma unroll
            for (int nt = 0; nt < 8; nt++) {
                const __nv_bfloat16* vp = Vb + (size_t)(nt*8 + qr)*QP + ks*16 + 2*qc;
                uint32_t bf2[2] = { ldb32(vp), ldb32(vp + 8) };
                mma_bf(o[nt], af, bf2);
            }
        }
        __syncwarp();
    }

    // ---- epilogue: O /= l, write ctx bf16 ----
    float inv0 = 1.f / l0, inv1 = 1.f / l1;
    const int r0 = q0 + wid*16 + qr;
    __nv_bfloat16* C0 = ctx + (size_t)(bb*SS + r0)*DD + hh*DHD + 2*qc;
    #pragma unroll
    for (int nt = 0; nt < 8; nt++) {
        *reinterpret_cast<uint32_t*>(C0 + nt*8)        = pack_bf16(o[nt][0]*inv0, o[nt][1]*inv0);
        *reinterpret_cast<uint32_t*>(C0 + 8*DD + nt*8) = pack_bf16(o[nt][2]*inv1, o[nt][3]*inv1);
    }
}

// =================== tf32 GEMM (pre-rounded inputs, no cvt) ===================
template<int BM, int BN, int WM, int WN, int EPI>
__global__ __launch_bounds__(256, 2)
void mma_gemm(const float* __restrict__ A, const float* __restrict__ Bm,
              float* __restrict__ C, const float* __restrict__ bias,
              int K, int lda, int ldb, int ldc)
{
    constexpr int S = 4;
    constexpr int PITCH = 20;
    constexpr int WARPS_N = BN/WN;
    constexpr int MT = WM/16, NT = WN/8;

    extern __shared__ float sm[];
    float* sA = sm;
    float* sB = sm + (size_t)S*BM*PITCH;

    const int tid = threadIdx.x;
    const int m0 = blockIdx.y * BM, n0 = blockIdx.x * BN;
    const float* Ab = A  + (size_t)m0*lda;
    const float* Bb = Bm + (size_t)n0*ldb;
    const int KT = K / 16;

    auto load_stage = [&](int kt, int st) {
        float* dA = sA + (size_t)st*BM*PITCH;
        float* dB = sB + (size_t)st*BN*PITCH;
        #pragma unroll
        for (int l = 0; l < (BM*4)/256; l++) {
            int ci = tid + l*256;
            int r = ci >> 2, c = ci & 3;
            cp16(dA + r*PITCH + c*4, Ab + (size_t)r*lda + kt*16 + c*4);
        }
        #pragma unroll
        for (int l = 0; l < (BN*4)/256; l++) {
            int ci = tid + l*256;
            int r = ci >> 2, c = ci & 3;
            cp16(dB + r*PITCH + c*4, Bb + (size_t)r*ldb + kt*16 + c*4);
        }
    };

    #pragma unroll
    for (int s = 0; s < S-1; s++) { if (s < KT) load_stage(s, s); CP_COMMIT(); }

    const int wid = tid >> 5, lane = tid & 31;
    const int wm = (wid / WARPS_N) * WM;
    const int wn = (wid % WARPS_N) * WN;
    const int qr = lane >> 2, qc = lane & 3;

    float acc[MT][NT][4];
    #pragma unroll
    for (int i=0;i<MT;i++) for (int j=0;j<NT;j++) for (int e=0;e<4;e++) acc[i][j][e]=0.f;

    for (int kt = 0; kt < KT; kt++) {
        cp_wait<S-2>();
        __syncthreads();
        const int nk = kt + S - 1;
        if (nk < KT) load_stage(nk, nk % S);
        CP_COMMIT();

        const float* As = sA + (size_t)(kt % S)*BM*PITCH;
        const float* Bs = sB + (size_t)(kt % S)*BN*PITCH;
        #pragma unroll
        for (int ks = 0; ks < 2; ks++) {
            uint32_t af[MT][4], bf[NT][2];
            #pragma unroll
            for (int mt = 0; mt < MT; mt++) {
                const float* p = As + (size_t)(wm + mt*16 + qr)*PITCH + ks*8 + qc;
                af[mt][0] = __float_as_uint(p[0]);
                af[mt][1] = __float_as_uint(p[8*PITCH]);
                af[mt][2] = __float_as_uint(p[4]);
                af[mt][3] = __float_as_uint(p[8*PITCH + 4]);
            }
            #pragma unroll
            for (int nt = 0; nt < NT; nt++) {
                const float* p = Bs + (size_t)(wn + nt*8 + qr)*PITCH + ks*8 + qc;
                bf[nt][0] = __float_as_uint(p[0]);
                bf[nt][1] = __float_as_uint(p[4]);
            }
            #pragma unroll
            for (int mt = 0; mt < MT; mt++)
                #pragma unroll
                for (int nt = 0; nt < NT; nt++)
                    mma_tf(acc[mt][nt], af[mt], bf[nt]);
        }
    }

    #pragma unroll
    for (int mt = 0; mt < MT; mt++) {
        #pragma unroll
        for (int nt = 0; nt < NT; nt++) {
            const int cc = n0 + wn + nt*8 + qc*2;
            float b0 = __ldg(&bias[cc]), b1 = __ldg(&bias[cc+1]);
            float x0 = acc[mt][nt][0] + b0;
            float x1 = acc[mt][nt][1] + b1;
            float x2 = acc[mt][nt][2] + b0;
            float x3 = acc[mt][nt][3] + b1;
            if (EPI == 2) {
                x0 = tf32r(gelu_exact(x0)); x1 = tf32r(gelu_exact(x1));
                x2 = tf32r(gelu_exact(x2)); x3 = tf32r(gelu_exact(x3));
            }
            const size_t r0 = (size_t)(m0 + wm + mt*16 + qr);
            *reinterpret_cast<float2*>(C + r0*ldc + cc)     = make_float2(x0, x1);
            *reinterpret_cast<float2*>(C + (r0+8)*ldc + cc) = make_float2(x2, x3);
        }
    }
}

// =================== block reduce / LN ===================
__device__ __forceinline__ float block_reduce(float val, bool ismax) {
    __shared__ float sh[32];
    int lane = threadIdx.x & 31, w = threadIdx.x >> 5;
    #pragma unroll
    for (int off=16; off>0; off>>=1) {
        float o = __shfl_xor_sync(0xffffffffu, val, off);
        val = ismax ? fmaxf(val, o) : (val + o);
    }
    if (lane == 0) sh[w] = val;
    __syncthreads();
    int nw = blockDim.x >> 5;
    if (w == 0) {
        float v = (lane < nw) ? sh[lane] : (ismax ? -3.4e38f : 0.f);
        #pragma unroll
        for (int off=16; off>0; off>>=1) {
            float o = __shfl_xor_sync(0xffffffffu, v, off);
            v = ismax ? fmaxf(v, o) : (v + o);
        }
        if (lane == 0) sh[0] = v;
    }
    __syncthreads();
    float r = sh[0];
    __syncthreads();
    return r;
}

// h = tf32_round(LN(x + res))
__global__ __launch_bounds__(256) void add_ln_k(
    const float* __restrict__ x, const float* __restrict__ res,
    const float* __restrict__ g, const float* __restrict__ b,
    float* __restrict__ y)
{
    size_t base = (size_t)blockIdx.x * DD;
    int t = threadIdx.x;
    float v[3];
    float s = 0.f;
    #pragma unroll
    for (int i=0;i<3;i++){
        int c = t + i*256;
        v[i] = x[base + c] + res[base + c];
        s += v[i];
    }
    s = block_reduce(s, false);
    float mu = s * (1.0f/DD);
    float q = 0.f;
    #pragma unroll
    for (int i=0;i<3;i++){ float d = v[i]-mu; q += d*d; }
    q = block_reduce(q, false);
    float rstd = rsqrtf(q * (1.0f/DD) + 1e-5f);
    #pragma unroll
    for (int i=0;i<3;i++){
        int c = t + i*256;
        y[base + c] = tf32r((v[i]-mu)*rstd*g[c] + b[c]);
    }
}

// =================== launch ===================
extern "C" void kernel_launch(void* const* d_in, const int* in_sizes, int n_in,
                              void* d_out, int out_size)
{
    const float* Q   = (const float*)d_in[0];
    const float* K   = (const float*)d_in[1];
    const float* V   = (const float*)d_in[2];
    const float* Wq  = (const float*)d_in[3];
    const float* bq  = (const float*)d_in[4];
    const float* Wk  = (const float*)d_in[5];
    const float* bk  = (const float*)d_in[6];
    const float* Wv  = (const float*)d_in[7];
    const float* bv  = (const float*)d_in[8];
    const float* Wo  = (const float*)d_in[9];
    const float* bo  = (const float*)d_in[10];
    const float* lng = (const float*)d_in[11];
    const float* lnb = (const float*)d_in[12];
    const float* W1  = (const float*)d_in[13];
    const float* b1  = (const float*)d_in[14];
    const float* W2  = (const float*)d_in[15];
    const float* b2  = (const float*)d_in[16];
    float* out = (float*)d_out;

    __nv_bfloat16 *xq,*xk,*xv,*qb,*kb,*vb,*vTb,*ctxb,*wqT,*wkT,*wvT,*woT;
    float *tmp,*h,*ff1,*w1T,*w2T;
    cudaGetSymbolAddress((void**)&xq,  g_xq);
    cudaGetSymbolAddress((void**)&xk,  g_xk);
    cudaGetSymbolAddress((void**)&xv,  g_xv);
    cudaGetSymbolAddress((void**)&qb,  g_qb);
    cudaGetSymbolAddress((void**)&kb,  g_kb);
    cudaGetSymbolAddress((void**)&vb,  g_vb);
    cudaGetSymbolAddress((void**)&vTb, g_vTb);
    cudaGetSymbolAddress((void**)&ctxb,g_ctxb);
    cudaGetSymbolAddress((void**)&tmp, g_tmp);
    cudaGetSymbolAddress((void**)&h,   g_h);
    cudaGetSymbolAddress((void**)&ff1, g_ff1);
    cudaGetSymbolAddress((void**)&wqT, g_wqT);
    cudaGetSymbolAddress((void**)&wkT, g_wkT);
    cudaGetSymbolAddress((void**)&wvT, g_wvT);
    cudaGetSymbolAddress((void**)&woT, g_woT);
    cudaGetSymbolAddress((void**)&w1T, g_w1T);
    cudaGetSymbolAddress((void**)&w2T, g_w2T);

    const int SM_TF  = 4*(128+128)*20*4;        // 81920
    const int SM_BF  = 3*(128+128)*40*2;        // 61440
    const int SM_FL  = (128*QP + 4*64*QP)*2;    // 55296
    cudaFuncSetAttribute((const void*)mma_gemm<128,128,64,32,1>, cudaFuncAttributeMaxDynamicSharedMemorySize, SM_TF);
    cudaFuncSetAttribute((const void*)mma_gemm<128,128,64,32,2>, cudaFuncAttributeMaxDynamicSharedMemorySize, SM_TF);
    cudaFuncSetAttribute((const void*)bgemm<0>, cudaFuncAttributeMaxDynamicSharedMemorySize, SM_BF);
    cudaFuncSetAttribute((const void*)bgemm<1>, cudaFuncAttributeMaxDynamicSharedMemorySize, SM_BF);
    cudaFuncSetAttribute((const void*)flash_k, cudaFuncAttributeMaxDynamicSharedMemorySize, SM_FL);

    const int NEL = BB*SS*DD;
    dim3 tb(32, 8);

    // 0) inputs -> bf16 ; weights -> transposed bf16 / tf32
    f2b_k<<<NEL/1024, 256>>>(Q, xq);
    f2b_k<<<NEL/1024, 256>>>(K, xk);
    f2b_k<<<NEL/1024, 256>>>(V, xv);
    transpose_t<0><<<dim3(DD/32, DD/32),  tb>>>(Wq, wqT, DD, DD);
    transpose_t<0><<<dim3(DD/32, DD/32),  tb>>>(Wk, wkT, DD, DD);
    transpose_t<0><<<dim3(DD/32, DD/32),  tb>>>(Wv, wvT, DD, DD);
    transpose_t<0><<<dim3(DD/32, DD/32),  tb>>>(Wo, woT, DD, DD);
    transpose_t<1><<<dim3(DFF/32, DD/32), tb>>>(W1, w1T, DD, DFF);
    transpose_t<1><<<dim3(DD/32, DFF/32), tb>>>(W2, w2T, DFF, DD);

    // 1) QKV projections (bf16)
    bgemm<1><<<dim3(DD/128, MROWS/128), 256, SM_BF>>>(xq, wqT, qb, bq, DD, DD, DD, DD);
    bgemm<1><<<dim3(DD/128, MROWS/128), 256, SM_BF>>>(xk, wkT, kb, bk, DD, DD, DD, DD);
    bgemm<1><<<dim3(DD/128, MROWS/128), 256, SM_BF>>>(xv, wvT, vb, bv, DD, DD, DD, DD);

    // 1b) v -> vT
    vtrans_k<<<dim3(SS/32, DHD/32, BB*HH), tb>>>(vb, vTb);

    // 2-4) fused flash attention -> ctx (bf16)
    flash_k<<<dim3(SS/128, BB*HH), 256, SM_FL>>>(qb, kb, vTb, ctxb);

    // 5) attn_out = ctx @ Wo^T + bo (bf16 in, fp32 out)
    bgemm<0><<<dim3(DD/128, MROWS/128), 256, SM_BF>>>(ctxb, woT, tmp, bo, DD, DD, DD, DD);

    // 6) h = LN(Q + attn_out), tf32-rounded
    add_ln_k<<<MROWS, 256>>>(tmp, Q, lng, lnb, h);

    // 7) ff1 = gelu(h @ W1^T + b1), tf32-rounded
    mma_gemm<128,128,64,32,2><<<dim3(DFF/128, MROWS/128), 256, SM_TF>>>(
        h, w1T, ff1, b1, DD, DD, DD, DFF);

    // 8) out = ff1 @ W2^T + b2
    mma_gemm<128,128,64,32,1><<<dim3(DD/128, MROWS/128), 256, SM_TF>>>(
        ff1, w2T, out, b2, DFF, DFF, DFF, DD);
}

// round 7
// speedup vs baseline: 5.7549x; 1.3395x over previous
#include <cuda_runtime.h>
#include <cuda_bf16.h>
#include <cuda_fp16.h>
#include <math.h>
#include <stdint.h>

// Problem constants
#define BB   4
#define SS   2048
#define DD   768
#define HH   12
#define DHD  64
#define DFF  3072
#define MROWS (BB*SS)          // 8192

// -------- scratch (device globals; no allocations allowed) --------
static __device__ __align__(16) __nv_bfloat16 g_xq [(size_t)BB*SS*DD];
static __device__ __align__(16) __nv_bfloat16 g_xk [(size_t)BB*SS*DD];
static __device__ __align__(16) __nv_bfloat16 g_xv [(size_t)BB*SS*DD];
static __device__ __align__(16) __nv_bfloat16 g_qb [(size_t)BB*SS*DD];
static __device__ __align__(16) __nv_bfloat16 g_kb [(size_t)BB*SS*DD];
static __device__ __align__(16) __nv_bfloat16 g_vb [(size_t)BB*SS*DD];
static __device__ __align__(16) __nv_bfloat16 g_vTb[(size_t)BB*HH*DHD*SS];
static __device__ __align__(16) __nv_bfloat16 g_ctxb[(size_t)BB*SS*DD];
static __device__ __align__(16) float  g_tmp[(size_t)BB*SS*DD];
static __device__ __align__(16) __half g_h  [(size_t)BB*SS*DD];
static __device__ __align__(16) __half g_ff1[(size_t)MROWS*DFF];
static __device__ __align__(16) __nv_bfloat16 g_wqT[(size_t)DD*DD];
static __device__ __align__(16) __nv_bfloat16 g_wkT[(size_t)DD*DD];
static __device__ __align__(16) __nv_bfloat16 g_wvT[(size_t)DD*DD];
static __device__ __align__(16) __nv_bfloat16 g_woT[(size_t)DD*DD];
static __device__ __align__(16) __half g_w1T[(size_t)DFF*DD];
static __device__ __align__(16) __half g_w2T[(size_t)DD*DFF];

__device__ __forceinline__ float gelu_exact(float x) {
    return 0.5f * x * (1.0f + erff(x * 0.7071067811865476f));
}

// ---------------- helpers ----------------
__device__ __forceinline__ uint32_t pack_bf16(float lo, float hi) {
    uint32_t r;
    asm("cvt.rn.bf16x2.f32 %0, %1, %2;" : "=r"(r) : "f"(hi), "f"(lo));
    return r;
}
__device__ __forceinline__ uint32_t pack_f16(float lo, float hi) {
    uint32_t r;
    asm("cvt.rn.f16x2.f32 %0, %1, %2;" : "=r"(r) : "f"(hi), "f"(lo));
    return r;
}
__device__ __forceinline__ uint32_t ldb32(const void* p) {
    return *reinterpret_cast<const uint32_t*>(p);
}
__device__ __forceinline__ void mma_bf(float* c, const uint32_t* a, const uint32_t* b) {
    asm volatile("mma.sync.aligned.m16n8k16.row.col.f32.bf16.bf16.f32 "
        "{%0,%1,%2,%3}, {%4,%5,%6,%7}, {%8,%9}, {%0,%1,%2,%3};"
        : "+f"(c[0]), "+f"(c[1]), "+f"(c[2]), "+f"(c[3])
        : "r"(a[0]), "r"(a[1]), "r"(a[2]), "r"(a[3]), "r"(b[0]), "r"(b[1]));
}
__device__ __forceinline__ void mma_fp(float* c, const uint32_t* a, const uint32_t* b) {
    asm volatile("mma.sync.aligned.m16n8k16.row.col.f32.f16.f16.f32 "
        "{%0,%1,%2,%3}, {%4,%5,%6,%7}, {%8,%9}, {%0,%1,%2,%3};"
        : "+f"(c[0]), "+f"(c[1]), "+f"(c[2]), "+f"(c[3])
        : "r"(a[0]), "r"(a[1]), "r"(a[2]), "r"(a[3]), "r"(b[0]), "r"(b[1]));
}
template<int N> __device__ __forceinline__ void cp_wait() {
    asm volatile("cp.async.wait_group %0;" :: "n"(N));
}
#define CP_COMMIT() asm volatile("cp.async.commit_group;")
__device__ __forceinline__ void cp16(void* smem_dst, const void* gsrc) {
    uint32_t d = (uint32_t)__cvta_generic_to_shared(smem_dst);
    asm volatile("cp.async.cg.shared.global [%0], [%1], 16;" :: "r"(d), "l"(gsrc));
}

// =================== fp32 -> bf16 copy ===================
__global__ __launch_bounds__(256) void f2b_k(const float* __restrict__ x,
                                             __nv_bfloat16* __restrict__ y)
{
    size_t i = ((size_t)blockIdx.x*256 + threadIdx.x) * 4;
    float4 v = *reinterpret_cast<const float4*>(x + i);
    uint2 o;
    o.x = pack_bf16(v.x, v.y);
    o.y = pack_bf16(v.z, v.w);
    *reinterpret_cast<uint2*>(y + i) = o;
}

// =================== transposes ===================
// MODE 0: out bf16; MODE 1: out fp16
template<int MODE>
__global__ __launch_bounds__(256) void transpose_t(const float* __restrict__ src,
                                                   void* __restrict__ dst, int R, int C)
{
    __shared__ float tile[32][33];
    const int c0 = blockIdx.x*32, r0 = blockIdx.y*32;
    const int x = threadIdx.x, y = threadIdx.y;
    #pragma unroll
    for (int i = 0; i < 32; i += 8) tile[y+i][x] = src[(size_t)(r0+y+i)*C + c0+x];
    __syncthreads();
    if (MODE == 0) {
        __nv_bfloat16* d = (__nv_bfloat16*)dst;
        #pragma unroll
        for (int i = 0; i < 32; i += 8)
            d[(size_t)(c0+y+i)*R + r0+x] = __float2bfloat16_rn(tile[x][y+i]);
    } else {
        __half* d = (__half*)dst;
        #pragma unroll
        for (int i = 0; i < 32; i += 8)
            d[(size_t)(c0+y+i)*R + r0+x] = __float2half_rn(tile[x][y+i]);
    }
}

// v bf16 [b*2048+s][h*64+d] -> vT bf16 [(b*12+h)*64+d][s]
__global__ __launch_bounds__(256) void vtrans_k(const __nv_bfloat16* __restrict__ v,
                                                __nv_bfloat16* __restrict__ vt)
{
    __shared__ __nv_bfloat16 tile[32][34];
    const int z = blockIdx.z, bb = z/HH, hh = z%HH;
    const int s0 = blockIdx.x*32, d0 = blockIdx.y*32;
    const int x = threadIdx.x, y = threadIdx.y;
    #pragma unroll
    for (int i = 0; i < 32; i += 8)
        tile[y+i][x] = v[(size_t)(bb*SS + s0 + y+i)*DD + hh*DHD + d0 + x];
    __syncthreads();
    #pragma unroll
    for (int i = 0; i < 32; i += 8)
        vt[(size_t)(z*DHD + d0 + y+i)*SS + s0 + x] = tile[x][y+i];
}

// =================== 16-bit GEMM: C = A[M,K] @ B[N,K]^T + bias ===================
// DT: 0=bf16, 1=fp16. OUT: 0=fp32, 1=bf16, 2=fp16. EPI: 1=bias, 2=bias+gelu.
// BM=BN=128, BK=32, 8 warps 64x32, 3-stage cp.async.
template<int DT, int OUT, int EPI>
__global__ __launch_bounds__(256, 2)
void gemm16(const uint16_t* __restrict__ A, const uint16_t* __restrict__ Bm,
            void* __restrict__ Cv, const float* __restrict__ bias,
            int K, int lda, int ldb, int ldc)
{
    constexpr int S = 3, PITCH = 40, BM = 128, BN = 128;
    extern __shared__ uint16_t smh[];
    uint16_t* sA = smh;
    uint16_t* sB = smh + (size_t)S*BM*PITCH;

    const int tid = threadIdx.x;
    const int m0 = blockIdx.y * BM, n0 = blockIdx.x * BN;
    const uint16_t* Ab = A  + (size_t)m0*lda;
    const uint16_t* Bb = Bm + (size_t)n0*ldb;
    const int KT = K / 32;

    auto load_stage = [&](int kt, int st) {
        uint16_t* dA = sA + (size_t)st*BM*PITCH;
        uint16_t* dB = sB + (size_t)st*BN*PITCH;
        #pragma unroll
        for (int l = 0; l < 2; l++) {
            int ci = tid + l*256;
            int r = ci >> 2, c = ci & 3;
            cp16(dA + r*PITCH + c*8, Ab + (size_t)r*lda + kt*32 + c*8);
            cp16(dB + r*PITCH + c*8, Bb + (size_t)r*ldb + kt*32 + c*8);
        }
    };

    #pragma unroll
    for (int s = 0; s < S-1; s++) { load_stage(s, s); CP_COMMIT(); }

    const int wid = tid >> 5, lane = tid & 31;
    const int wm = (wid >> 2) * 64;
    const int wn = (wid & 3) * 32;
    const int qr = lane >> 2, qc = lane & 3;

    float acc[4][4][4];
    #pragma unroll
    for (int i=0;i<4;i++) for (int j=0;j<4;j++) for (int e=0;e<4;e++) acc[i][j][e]=0.f;

    for (int kt = 0; kt < KT; kt++) {
        cp_wait<1>();
        __syncthreads();
        const int nk = kt + S - 1;
        if (nk < KT) load_stage(nk, nk % S);
        CP_COMMIT();

        const uint16_t* As = sA + (size_t)(kt % S)*BM*PITCH;
        const uint16_t* Bs = sB + (size_t)(kt % S)*BN*PITCH;
        #pragma unroll
        for (int ks = 0; ks < 2; ks++) {
            uint32_t af[4][4], bf[4][2];
            #pragma unroll
            for (int mt = 0; mt < 4; mt++) {
                const uint16_t* p = As + (size_t)(wm + mt*16 + qr)*PITCH + ks*16 + 2*qc;
                af[mt][0] = ldb32(p);
                af[mt][1] = ldb32(p + 8*PITCH);
                af[mt][2] = ldb32(p + 8);
                af[mt][3] = ldb32(p + 8*PITCH + 8);
            }
            #pragma unroll
            for (int nt = 0; nt < 4; nt++) {
                const uint16_t* p = Bs + (size_t)(wn + nt*8 + qr)*PITCH + ks*16 + 2*qc;
                bf[nt][0] = ldb32(p);
                bf[nt][1] = ldb32(p + 8);
            }
            #pragma unroll
            for (int mt = 0; mt < 4; mt++)
                #pragma unroll
                for (int nt = 0; nt < 4; nt++) {
                    if (DT == 0) mma_bf(acc[mt][nt], af[mt], bf[nt]);
                    else         mma_fp(acc[mt][nt], af[mt], bf[nt]);
                }
        }
        __syncthreads();
    }

    #pragma unroll
    for (int mt = 0; mt < 4; mt++) {
        #pragma unroll
        for (int nt = 0; nt < 4; nt++) {
            const int cc = n0 + wn + nt*8 + qc*2;
            float b0 = __ldg(&bias[cc]), b1 = __ldg(&bias[cc+1]);
            float x0 = acc[mt][nt][0] + b0, x1 = acc[mt][nt][1] + b1;
            float x2 = acc[mt][nt][2] + b0, x3 = acc[mt][nt][3] + b1;
            if (EPI == 2) {
                x0 = gelu_exact(x0); x1 = gelu_exact(x1);
                x2 = gelu_exact(x2); x3 = gelu_exact(x3);
            }
            const size_t r0 = (size_t)(m0 + wm + mt*16 + qr);
            if (OUT == 0) {
                float* Cf = (float*)Cv;
                *reinterpret_cast<float2*>(Cf + r0*ldc + cc)     = make_float2(x0, x1);
                *reinterpret_cast<float2*>(Cf + (r0+8)*ldc + cc) = make_float2(x2, x3);
            } else if (OUT == 1) {
                __nv_bfloat16* Cb = (__nv_bfloat16*)Cv;
                *reinterpret_cast<uint32_t*>(Cb + r0*ldc + cc)     = pack_bf16(x0, x1);
                *reinterpret_cast<uint32_t*>(Cb + (r0+8)*ldc + cc) = pack_bf16(x2, x3);
            } else {
                __half* Ch = (__half*)Cv;
                *reinterpret_cast<uint32_t*>(Ch + r0*ldc + cc)     = pack_f16(x0, x1);
                *reinterpret_cast<uint32_t*>(Ch + (r0+8)*ldc + cc) = pack_f16(x2, x3);
            }
        }
    }
}

// =================== fused flash attention (bf16 mma) ===================
#define QP 72

__global__ __launch_bounds__(256, 2)
void flash_k(const __nv_bfloat16* __restrict__ qg, const __nv_bfloat16* __restrict__ kg,
             const __nv_bfloat16* __restrict__ vtg, __nv_bfloat16* __restrict__ ctx)
{
    extern __shared__ __nv_bfloat16 smb[];
    __nv_bfloat16* Qs = smb;                 // [128][QP], reused as P buffer
    __nv_bfloat16* Ks = smb + 128*QP;        // [2][64][QP]
    __nv_bfloat16* Vs = Ks + 2*64*QP;        // [2][64][QP]

    const int tid = threadIdx.x, wid = tid >> 5, lane = tid & 31;
    const int qr = lane >> 2, qc = lane & 3;
    const int bh = blockIdx.y;
    const int bb = bh / HH, hh = bh % HH;
    const int q0 = blockIdx.x * 128;

    const __nv_bfloat16* Qg = qg  + (size_t)(bb*SS + q0)*DD + hh*DHD;
    const __nv_bfloat16* Kg = kg  + (size_t)(bb*SS)*DD + hh*DHD;
    const __nv_bfloat16* Vg = vtg + (size_t)bh*DHD*SS;

    #pragma unroll
    for (int l = 0; l < 4; l++) {
        int ci = tid + l*256;
        int r = ci >> 3, c = ci & 7;
        cp16(Qs + r*QP + c*8, Qg + (size_t)r*DD + c*8);
    }
    CP_COMMIT();
    #pragma unroll
    for (int l = 0; l < 2; l++) {
        int ci = tid + l*256;
        int r = ci >> 3, c = ci & 7;
        cp16(Ks + r*QP + c*8, Kg + (size_t)r*DD + c*8);
        cp16(Vs + r*QP + c*8, Vg + (size_t)r*SS + c*8);
    }
    CP_COMMIT();

    cp_wait<1>();
    __syncthreads();

    uint32_t qf[4][4];
    {
        const __nv_bfloat16* Qr = Qs + (size_t)(wid*16 + qr)*QP + 2*qc;
        #pragma unroll
        for (int ks = 0; ks < 4; ks++) {
            qf[ks][0] = ldb32(Qr + ks*16);
            qf[ks][1] = ldb32(Qr + 8*QP + ks*16);
            qf[ks][2] = ldb32(Qr + ks*16 + 8);
            qf[ks][3] = ldb32(Qr + 8*QP + ks*16 + 8);
        }
    }

    float m0v = -3.4e38f, m1v = -3.4e38f, l0 = 0.f, l1 = 0.f;
    float o[8][4];
    #pragma unroll
    for (int nt = 0; nt < 8; nt++)
        #pragma unroll
        for (int e = 0; e < 4; e++) o[nt][e] = 0.f;

    const int NJ = SS / 64;
    for (int j = 0; j < NJ; j++) {
        cp_wait<0>();
        __syncthreads();
        if (j + 1 < NJ) {
            __nv_bfloat16* Kn = Ks + ((j+1)&1)*64*QP;
            __nv_bfloat16* Vn = Vs + ((j+1)&1)*64*QP;
            const __nv_bfloat16* Kgn = Kg + (size_t)(j+1)*64*DD;
            const __nv_bfloat16* Vgn = Vg + (j+1)*64;
            #pragma unroll
            for (int l = 0; l < 2; l++) {
                int ci = tid + l*256;
                int r = ci >> 3, c = ci & 7;
                cp16(Kn + r*QP + c*8, Kgn + (size_t)r*DD + c*8);
                cp16(Vn + r*QP + c*8, Vgn + (size_t)r*SS + c*8);
            }
        }
        CP_COMMIT();

        const __nv_bfloat16* Kb = Ks + (j&1)*64*QP;
        const __nv_bfloat16* Vb = Vs + (j&1)*64*QP;

        float s[8][4];
        #pragma unroll
        for (int nt = 0; nt < 8; nt++)
            #pragma unroll
            for (int e = 0; e < 4; e++) s[nt][e] = 0.f;
        #pragma unroll
        for (int ks = 0; ks < 4; ks++) {
            #pragma unroll
            for (int nt = 0; nt < 8; nt++) {
                const __nv_bfloat16* p = Kb + (size_t)(nt*8 + qr)*QP + ks*16 + 2*qc;
                uint32_t kf[2] = { ldb32(p), ldb32(p + 8) };
                mma_bf(s[nt], qf[ks], kf);
            }
        }

        float mx0 = -3.4e38f, mx1 = -3.4e38f;
        #pragma unroll
        for (int nt = 0; nt < 8; nt++) {
            #pragma unroll
            for (int e = 0; e < 4; e++) s[nt][e] *= 0.125f;
            mx0 = fmaxf(mx0, fmaxf(s[nt][0], s[nt][1]));
            mx1 = fmaxf(mx1, fmaxf(s[nt][2], s[nt][3]));
        }
        #pragma unroll
        for (int off = 1; off <= 2; off <<= 1) {
            mx0 = fmaxf(mx0, __shfl_xor_sync(0xffffffffu, mx0, off));
            mx1 = fmaxf(mx1, __shfl_xor_sync(0xffffffffu, mx1, off));
        }
        float mn0 = fmaxf(m0v, mx0), mn1 = fmaxf(m1v, mx1);
        float a0 = __expf(m0v - mn0), a1 = __expf(m1v - mn1);
        m0v = mn0; m1v = mn1;
        float sum0 = 0.f, sum1 = 0.f;
        #pragma unroll
        for (int nt = 0; nt < 8; nt++) {
            s[nt][0] = __expf(s[nt][0] - mn0); sum0 += s[nt][0];
            s[nt][1] = __expf(s[nt][1] - mn0); sum0 += s[nt][1];
            s[nt][2] = __expf(s[nt][2] - mn1); sum1 += s[nt][2];
            s[nt][3] = __expf(s[nt][3] - mn1); sum1 += s[nt][3];
        }
        #pragma unroll
        for (int off = 1; off <= 2; off <<= 1) {
            sum0 += __shfl_xor_sync(0xffffffffu, sum0, off);
            sum1 += __shfl_xor_sync(0xffffffffu, sum1, off);
        }
        l0 = l0*a0 + sum0;
        l1 = l1*a1 + sum1;
        #pragma unroll
        for (int nt = 0; nt < 8; nt++) {
            o[nt][0] *= a0; o[nt][1] *= a0;
            o[nt][2] *= a1; o[nt][3] *= a1;
        }

        __nv_bfloat16* Pw = Qs + (size_t)(wid*16)*QP;
        __syncwarp();
        #pragma unroll
        for (int nt = 0; nt < 8; nt++) {
            *reinterpret_cast<uint32_t*>(Pw + (size_t)qr*QP     + nt*8 + 2*qc) = pack_bf16(s[nt][0], s[nt][1]);
            *reinterpret_cast<uint32_t*>(Pw + (size_t)(qr+8)*QP + nt*8 + 2*qc) = pack_bf16(s[nt][2], s[nt][3]);
        }
        __syncwarp();

        #pragma unroll
        for (int ks = 0; ks < 4; ks++) {
            uint32_t af[4];
            const __nv_bfloat16* pp = Pw + (size_t)qr*QP + ks*16 + 2*qc;
            af[0] = ldb32(pp);
            af[1] = ldb32(pp + 8*QP);
            af[2] = ldb32(pp + 8);
            af[3] = ldb32(pp + 8*QP + 8);
            #pragma unroll
            for (int nt = 0; nt < 8; nt++) {
                const __nv_bfloat16* vp = Vb + (size_t)(nt*8 + qr)*QP + ks*16 + 2*qc;
                uint32_t bf2[2] = { ldb32(vp), ldb32(vp + 8) };
                mma_bf(o[nt], af, bf2);
            }
        }
        __syncwarp();
    }

    float inv0 = 1.f / l0, inv1 = 1.f / l1;
    const int r0 = q0 + wid*16 + qr;
    __nv_bfloat16* C0 = ctx + (size_t)(bb*SS + r0)*DD + hh*DHD + 2*qc;
    #pragma unroll
    for (int nt = 0; nt < 8; nt++) {
        *reinterpret_cast<uint32_t*>(C0 + nt*8)        = pack_bf16(o[nt][0]*inv0, o[nt][1]*inv0);
        *reinterpret_cast<uint32_t*>(C0 + 8*DD + nt*8) = pack_bf16(o[nt][2]*inv1, o[nt][3]*inv1);
    }
}

// =================== block reduce / LN ===================
__device__ __forceinline__ float block_reduce(float val, bool ismax) {
    __shared__ float sh[32];
    int lane = threadIdx.x & 31, w = threadIdx.x >> 5;
    #pragma unroll
    for (int off=16; off>0; off>>=1) {
        float o = __shfl_xor_sync(0xffffffffu, val, off);
        val = ismax ? fmaxf(val, o) : (val + o);
    }
    if (lane == 0) sh[w] = val;
    __syncthreads();
    int nw = blockDim.x >> 5;
    if (w == 0) {
        float v = (lane < nw) ? sh[lane] : (ismax ? -3.4e38f : 0.f);
        #pragma unroll
        for (int off=16; off>0; off>>=1) {
            float o = __shfl_xor_sync(0xffffffffu, v, off);
            v = ismax ? fmaxf(v, o) : (v + o);
        }
        if (lane == 0) sh[0] = v;
    }
    __syncthreads();
    float r = sh[0];
    __syncthreads();
    return r;
}

// h = fp16(LN(x + res))
__global__ __launch_bounds__(256) void add_ln_k(
    const float* __restrict__ x, const float* __restrict__ res,
    const float* __restrict__ g, const float* __restrict__ b,
    __half* __restrict__ y)
{
    size_t base = (size_t)blockIdx.x * DD;
    int t = threadIdx.x;
    float v[3];
    float s = 0.f;
    #pragma unroll
    for (int i=0;i<3;i++){
        int c = t + i*256;
        v[i] = x[base + c] + res[base + c];
        s += v[i];
    }
    s = block_reduce(s, false);
    float mu = s * (1.0f/DD);
    float q = 0.f;
    #pragma unroll
    for (int i=0;i<3;i++){ float d = v[i]-mu; q += d*d; }
    q = block_reduce(q, false);
    float rstd = rsqrtf(q * (1.0f/DD) + 1e-5f);
    #pragma unroll
    for (int i=0;i<3;i++){
        int c = t + i*256;
        y[base + c] = __float2half_rn((v[i]-mu)*rstd*g[c] + b[c]);
    }
}

// =================== launch ===================
extern "C" void kernel_launch(void* const* d_in, const int* in_sizes, int n_in,
                              void* d_out, int out_size)
{
    const float* Q   = (const float*)d_in[0];
    const float* K   = (const float*)d_in[1];
    const float* V   = (const float*)d_in[2];
    const float* Wq  = (const float*)d_in[3];
    const float* bq  = (const float*)d_in[4];
    const float* Wk  = (const float*)d_in[5];
    const float* bk  = (const float*)d_in[6];
    const float* Wv  = (const float*)d_in[7];
    const float* bv  = (const float*)d_in[8];
    const float* Wo  = (const float*)d_in[9];
    const float* bo  = (const float*)d_in[10];
    const float* lng = (const float*)d_in[11];
    const float* lnb = (const float*)d_in[12];
    const float* W1  = (const float*)d_in[13];
    const float* b1  = (const float*)d_in[14];
    const float* W2  = (const float*)d_in[15];
    const float* b2  = (const float*)d_in[16];
    float* out = (float*)d_out;

    __nv_bfloat16 *xq,*xk,*xv,*qb,*kb,*vb,*vTb,*ctxb,*wqT,*wkT,*wvT,*woT;
    float *tmp;
    __half *h,*ff1,*w1T,*w2T;
    cudaGetSymbolAddress((void**)&xq,  g_xq);
    cudaGetSymbolAddress((void**)&xk,  g_xk);
    cudaGetSymbolAddress((void**)&xv,  g_xv);
    cudaGetSymbolAddress((void**)&qb,  g_qb);
    cudaGetSymbolAddress((void**)&kb,  g_kb);
    cudaGetSymbolAddress((void**)&vb,  g_vb);
    cudaGetSymbolAddress((void**)&vTb, g_vTb);
    cudaGetSymbolAddress((void**)&ctxb,g_ctxb);
    cudaGetSymbolAddress((void**)&tmp, g_tmp);
    cudaGetSymbolAddress((void**)&h,   g_h);
    cudaGetSymbolAddress((void**)&ff1, g_ff1);
    cudaGetSymbolAddress((void**)&wqT, g_wqT);
    cudaGetSymbolAddress((void**)&wkT, g_wkT);
    cudaGetSymbolAddress((void**)&wvT, g_wvT);
    cudaGetSymbolAddress((void**)&woT, g_woT);
    cudaGetSymbolAddress((void**)&w1T, g_w1T);
    cudaGetSymbolAddress((void**)&w2T, g_w2T);

    const int SM_G16 = 3*(128+128)*40*2;        // 61440
    const int SM_FL  = (128*QP + 4*64*QP)*2;    // 55296
    cudaFuncSetAttribute((const void*)gemm16<0,1,1>, cudaFuncAttributeMaxDynamicSharedMemorySize, SM_G16);
    cudaFuncSetAttribute((const void*)gemm16<0,0,1>, cudaFuncAttributeMaxDynamicSharedMemorySize, SM_G16);
    cudaFuncSetAttribute((const void*)gemm16<1,2,2>, cudaFuncAttributeMaxDynamicSharedMemorySize, SM_G16);
    cudaFuncSetAttribute((const void*)gemm16<1,0,1>, cudaFuncAttributeMaxDynamicSharedMemorySize, SM_G16);
    cudaFuncSetAttribute((const void*)flash_k, cudaFuncAttributeMaxDynamicSharedMemorySize, SM_FL);

    const int NEL = BB*SS*DD;
    dim3 tb(32, 8);

    // 0) inputs -> bf16 ; weights -> transposed bf16 / fp16
    f2b_k<<<NEL/1024, 256>>>(Q, xq);
    f2b_k<<<NEL/1024, 256>>>(K, xk);
    f2b_k<<<NEL/1024, 256>>>(V, xv);
    transpose_t<0><<<dim3(DD/32, DD/32),  tb>>>(Wq, wqT, DD, DD);
    transpose_t<0><<<dim3(DD/32, DD/32),  tb>>>(Wk, wkT, DD, DD);
    transpose_t<0><<<dim3(DD/32, DD/32),  tb>>>(Wv, wvT, DD, DD);
    transpose_t<0><<<dim3(DD/32, DD/32),  tb>>>(Wo, woT, DD, DD);
    transpose_t<1><<<dim3(DFF/32, DD/32), tb>>>(W1, w1T, DD, DFF);
    transpose_t<1><<<dim3(DD/32, DFF/32), tb>>>(W2, w2T, DFF, DD);

    // 1) QKV projections (bf16 -> bf16)
    gemm16<0,1,1><<<dim3(DD/128, MROWS/128), 256, SM_G16>>>(
        (const uint16_t*)xq, (const uint16_t*)wqT, qb, bq, DD, DD, DD, DD);
    gemm16<0,1,1><<<dim3(DD/128, MROWS/128), 256, SM_G16>>>(
        (const uint16_t*)xk, (const uint16_t*)wkT, kb, bk, DD, DD, DD, DD);
    gemm16<0,1,1><<<dim3(DD/128, MROWS/128), 256, SM_G16>>>(
        (const uint16_t*)xv, (const uint16_t*)wvT, vb, bv, DD, DD, DD, DD);

    // 1b) v -> vT
    vtrans_k<<<dim3(SS/32, DHD/32, BB*HH), tb>>>(vb, vTb);

    // 2-4) fused flash attention -> ctx (bf16)
    flash_k<<<dim3(SS/128, BB*HH), 256, SM_FL>>>(qb, kb, vTb, ctxb);

    // 5) attn_out = ctx @ Wo^T + bo (bf16 -> fp32)
    gemm16<0,0,1><<<dim3(DD/128, MROWS/128), 256, SM_G16>>>(
        (const uint16_t*)ctxb, (const uint16_t*)woT, tmp, bo, DD, DD, DD, DD);

    // 6) h = fp16(LN(Q + attn_out))
    add_ln_k<<<MROWS, 256>>>(tmp, Q, lng, lnb, h);

    // 7) ff1 = fp16(gelu(h @ W1^T + b1))  (fp16 mma)
    gemm16<1,2,2><<<dim3(DFF/128, MROWS/128), 256, SM_G16>>>(
        (const uint16_t*)h, (const uint16_t*)w1T, ff1, b1, DD, DD, DD, DFF);

    // 8) out = ff1 @ W2^T + b2 (fp16 -> fp32)
    gemm16<1,0,1><<<dim3(DD/128, MROWS/128), 256, SM_G16>>>(
        (const uint16_t*)ff1, (const uint16_t*)w2T, out, b2, DFF, DFF, DFF, DD);
}

// round 8
// speedup vs baseline: 6.2300x; 1.0826x over previous
#include <cuda_runtime.h>
#include <cuda_bf16.h>
#include <cuda_fp16.h>
#include <math.h>
#include <stdint.h>

// Problem constants
#define BB   4
#define SS   2048
#define DD   768
#define HH   12
#define DHD  64
#define DFF  3072
#define MROWS (BB*SS)          // 8192

// -------- scratch (device globals; no allocations allowed) --------
static __device__ __align__(16) __nv_bfloat16 g_xq [(size_t)BB*SS*DD];
static __device__ __align__(16) __nv_bfloat16 g_xk [(size_t)BB*SS*DD];
static __device__ __align__(16) __nv_bfloat16 g_xv [(size_t)BB*SS*DD];
static __device__ __align__(16) __nv_bfloat16 g_qb [(size_t)BB*SS*DD];
static __device__ __align__(16) __nv_bfloat16 g_kb [(size_t)BB*SS*DD];
static __device__ __align__(16) __nv_bfloat16 g_vb [(size_t)BB*SS*DD];
static __device__ __align__(16) __nv_bfloat16 g_vTb[(size_t)BB*HH*DHD*SS];
static __device__ __align__(16) __nv_bfloat16 g_ctxb[(size_t)BB*SS*DD];
static __device__ __align__(16) float  g_tmp[(size_t)BB*SS*DD];
static __device__ __align__(16) __half g_h  [(size_t)BB*SS*DD];
static __device__ __align__(16) __half g_ff1[(size_t)MROWS*DFF];
static __device__ __align__(16) __nv_bfloat16 g_wqT[(size_t)DD*DD];
static __device__ __align__(16) __nv_bfloat16 g_wkT[(size_t)DD*DD];
static __device__ __align__(16) __nv_bfloat16 g_wvT[(size_t)DD*DD];
static __device__ __align__(16) __nv_bfloat16 g_woT[(size_t)DD*DD];
static __device__ __align__(16) __half g_w1T[(size_t)DFF*DD];
static __device__ __align__(16) __half g_w2T[(size_t)DD*DFF];

__device__ __forceinline__ float gelu_exact(float x) {
    return 0.5f * x * (1.0f + erff(x * 0.7071067811865476f));
}

// ---------------- helpers ----------------
__device__ __forceinline__ uint32_t pack_bf16(float lo, float hi) {
    uint32_t r;
    asm("cvt.rn.bf16x2.f32 %0, %1, %2;" : "=r"(r) : "f"(hi), "f"(lo));
    return r;
}
__device__ __forceinline__ uint32_t pack_f16(float lo, float hi) {
    uint32_t r;
    asm("cvt.rn.f16x2.f32 %0, %1, %2;" : "=r"(r) : "f"(hi), "f"(lo));
    return r;
}
__device__ __forceinline__ void mma_bf(float* c, const uint32_t* a, const uint32_t* b) {
    asm volatile("mma.sync.aligned.m16n8k16.row.col.f32.bf16.bf16.f32 "
        "{%0,%1,%2,%3}, {%4,%5,%6,%7}, {%8,%9}, {%0,%1,%2,%3};"
        : "+f"(c[0]), "+f"(c[1]), "+f"(c[2]), "+f"(c[3])
        : "r"(a[0]), "r"(a[1]), "r"(a[2]), "r"(a[3]), "r"(b[0]), "r"(b[1]));
}
__device__ __forceinline__ void mma_fp(float* c, const uint32_t* a, const uint32_t* b) {
    asm volatile("mma.sync.aligned.m16n8k16.row.col.f32.f16.f16.f32 "
        "{%0,%1,%2,%3}, {%4,%5,%6,%7}, {%8,%9}, {%0,%1,%2,%3};"
        : "+f"(c[0]), "+f"(c[1]), "+f"(c[2]), "+f"(c[3])
        : "r"(a[0]), "r"(a[1]), "r"(a[2]), "r"(a[3]), "r"(b[0]), "r"(b[1]));
}
// ldmatrix x4: lanes 0-7 -> matrix0 rows, 8-15 -> m1, 16-23 -> m2, 24-31 -> m3.
__device__ __forceinline__ void ldmx4(uint32_t* r, const void* p) {
    uint32_t a = (uint32_t)__cvta_generic_to_shared(p);
    asm volatile("ldmatrix.sync.aligned.m8n8.x4.shared.b16 {%0,%1,%2,%3}, [%4];"
        : "=r"(r[0]), "=r"(r[1]), "=r"(r[2]), "=r"(r[3]) : "r"(a));
}
template<int N> __device__ __forceinline__ void cp_wait() {
    asm volatile("cp.async.wait_group %0;" :: "n"(N));
}
#define CP_COMMIT() asm volatile("cp.async.commit_group;")
__device__ __forceinline__ void cp16(void* smem_dst, const void* gsrc) {
    uint32_t d = (uint32_t)__cvta_generic_to_shared(smem_dst);
    asm volatile("cp.async.cg.shared.global [%0], [%1], 16;" :: "r"(d), "l"(gsrc));
}

// =================== fp32 -> bf16 copy ===================
__global__ __launch_bounds__(256) void f2b_k(const float* __restrict__ x,
                                             __nv_bfloat16* __restrict__ y)
{
    size_t i = ((size_t)blockIdx.x*256 + threadIdx.x) * 4;
    float4 v = *reinterpret_cast<const float4*>(x + i);
    uint2 o;
    o.x = pack_bf16(v.x, v.y);
    o.y = pack_bf16(v.z, v.w);
    *reinterpret_cast<uint2*>(y + i) = o;
}

// =================== transposes ===================
template<int MODE>   // 0: bf16 out, 1: fp16 out
__global__ __launch_bounds__(256) void transpose_t(const float* __restrict__ src,
                                                   void* __restrict__ dst, int R, int C)
{
    __shared__ float tile[32][33];
    const int c0 = blockIdx.x*32, r0 = blockIdx.y*32;
    const int x = threadIdx.x, y = threadIdx.y;
    #pragma unroll
    for (int i = 0; i < 32; i += 8) tile[y+i][x] = src[(size_t)(r0+y+i)*C + c0+x];
    __syncthreads();
    if (MODE == 0) {
        __nv_bfloat16* d = (__nv_bfloat16*)dst;
        #pragma unroll
        for (int i = 0; i < 32; i += 8)
            d[(size_t)(c0+y+i)*R + r0+x] = __float2bfloat16_rn(tile[x][y+i]);
    } else {
        __half* d = (__half*)dst;
        #pragma unroll
        for (int i = 0; i < 32; i += 8)
            d[(size_t)(c0+y+i)*R + r0+x] = __float2half_rn(tile[x][y+i]);
    }
}

__global__ __launch_bounds__(256) void vtrans_k(const __nv_bfloat16* __restrict__ v,
                                                __nv_bfloat16* __restrict__ vt)
{
    __shared__ __nv_bfloat16 tile[32][34];
    const int z = blockIdx.z, bb = z/HH, hh = z%HH;
    const int s0 = blockIdx.x*32, d0 = blockIdx.y*32;
    const int x = threadIdx.x, y = threadIdx.y;
    #pragma unroll
    for (int i = 0; i < 32; i += 8)
        tile[y+i][x] = v[(size_t)(bb*SS + s0 + y+i)*DD + hh*DHD + d0 + x];
    __syncthreads();
    #pragma unroll
    for (int i = 0; i < 32; i += 8)
        vt[(size_t)(z*DHD + d0 + y+i)*SS + s0 + x] = tile[x][y+i];
}

// =================== 16-bit GEMM body (ldmatrix mainloop) ===================
// C = A[M,K] @ B[N,K]^T + bias. DT 0=bf16 1=fp16. OUT 0=f32 1=bf16 2=f16.
template<int DT, int OUT, int EPI, int BM, int BN, int WARPS_M, int WARPS_N>
__device__ __forceinline__ void gemm_body(
    const uint16_t* __restrict__ A, const uint16_t* __restrict__ Bm,
    void* __restrict__ Cv, const float* __restrict__ bias,
    int K, int lda, int ldb, int ldc, int m0, int n0, uint16_t* smh)
{
    constexpr int S = 3, PITCH = 40;
    constexpr int WM = BM/WARPS_M, WN = BN/WARPS_N;
    constexpr int MT = WM/16, NT = WN/8;
    uint16_t* sA = smh;
    uint16_t* sB = smh + (size_t)S*BM*PITCH;

    const int tid = threadIdx.x;
    const uint16_t* Ab = A  + (size_t)m0*lda;
    const uint16_t* Bb = Bm + (size_t)n0*ldb;
    const int KT = K / 32;

    auto load_stage = [&](int kt, int st) {
        uint16_t* dA = sA + (size_t)st*BM*PITCH;
        uint16_t* dB = sB + (size_t)st*BN*PITCH;
        #pragma unroll
        for (int l = 0; l < (BM*4)/256; l++) {
            int ci = tid + l*256;
            int r = ci >> 2, c = ci & 3;
            cp16(dA + r*PITCH + c*8, Ab + (size_t)r*lda + kt*32 + c*8);
        }
        #pragma unroll
        for (int l = 0; l < (BN*4)/256; l++) {
            int ci = tid + l*256;
            int r = ci >> 2, c = ci & 3;
            cp16(dB + r*PITCH + c*8, Bb + (size_t)r*ldb + kt*32 + c*8);
        }
    };

    #pragma unroll
    for (int s = 0; s < S-1; s++) { load_stage(s, s); CP_COMMIT(); }

    const int wid = tid >> 5, lane = tid & 31;
    const int wm = (wid / WARPS_N) * WM;
    const int wn = (wid % WARPS_N) * WN;
    const int qr = lane >> 2, qc = lane & 3;
    // ldmatrix lane addressing (A-operand and B-operand patterns)
    const int aar = wm + ((lane & 8) ? 8 : 0) + (lane & 7);
    const int aac = (lane & 16) ? 8 : 0;
    const int bbr = wn + ((lane & 16) ? 8 : 0) + (lane & 7);
    const int bbc = (lane & 8) ? 8 : 0;

    float acc[MT][NT][4];
    #pragma unroll
    for (int i=0;i<MT;i++) for (int j=0;j<NT;j++) for (int e=0;e<4;e++) acc[i][j][e]=0.f;

    for (int kt = 0; kt < KT; kt++) {
        cp_wait<1>();
        __syncthreads();
        const int nk = kt + S - 1;
        if (nk < KT) load_stage(nk, nk % S);
        CP_COMMIT();

        const uint16_t* As = sA + (size_t)(kt % S)*BM*PITCH;
        const uint16_t* Bs = sB + (size_t)(kt % S)*BN*PITCH;
        #pragma unroll
        for (int ks = 0; ks < 2; ks++) {
            uint32_t af[MT][4];
            #pragma unroll
            for (int mt = 0; mt < MT; mt++)
                ldmx4(af[mt], As + (size_t)(aar + mt*16)*PITCH + ks*16 + aac);
            #pragma unroll
            for (int ntp = 0; ntp < NT/2; ntp++) {
                uint32_t t[4];
                ldmx4(t, Bs + (size_t)(bbr + ntp*16)*PITCH + ks*16 + bbc);
                #pragma unroll
                for (int mt = 0; mt < MT; mt++) {
                    if (DT == 0) { mma_bf(acc[mt][2*ntp], af[mt], t); mma_bf(acc[mt][2*ntp+1], af[mt], t+2); }
                    else         { mma_fp(acc[mt][2*ntp], af[mt], t); mma_fp(acc[mt][2*ntp+1], af[mt], t+2); }
                }
            }
        }
    }

    #pragma unroll
    for (int mt = 0; mt < MT; mt++) {
        #pragma unroll
        for (int nt = 0; nt < NT; nt++) {
            const int cc = n0 + wn + nt*8 + qc*2;
            float b0 = __ldg(&bias[cc]), b1 = __ldg(&bias[cc+1]);
            float x0 = acc[mt][nt][0] + b0, x1 = acc[mt][nt][1] + b1;
            float x2 = acc[mt][nt][2] + b0, x3 = acc[mt][nt][3] + b1;
            if (EPI == 2) {
                x0 = gelu_exact(x0); x1 = gelu_exact(x1);
                x2 = gelu_exact(x2); x3 = gelu_exact(x3);
            }
            const size_t r0 = (size_t)(m0 + wm + mt*16 + qr);
            if (OUT == 0) {
                float* Cf = (float*)Cv;
                *reinterpret_cast<float2*>(Cf + r0*ldc + cc)     = make_float2(x0, x1);
                *reinterpret_cast<float2*>(Cf + (r0+8)*ldc + cc) = make_float2(x2, x3);
            } else if (OUT == 1) {
                __nv_bfloat16* Cb = (__nv_bfloat16*)Cv;
                *reinterpret_cast<uint32_t*>(Cb + r0*ldc + cc)     = pack_bf16(x0, x1);
                *reinterpret_cast<uint32_t*>(Cb + (r0+8)*ldc + cc) = pack_bf16(x2, x3);
            } else {
                __half* Ch = (__half*)Cv;
                *reinterpret_cast<uint32_t*>(Ch + r0*ldc + cc)     = pack_f16(x0, x1);
                *reinterpret_cast<uint32_t*>(Ch + (r0+8)*ldc + cc) = pack_f16(x2, x3);
            }
        }
    }
}

template<int DT, int OUT, int EPI, int BM, int BN, int WARPS_M, int WARPS_N>
__global__ __launch_bounds__(256, 2)
void gemm16_k(const uint16_t* __restrict__ A, const uint16_t* __restrict__ Bm,
              void* __restrict__ Cv, const float* __restrict__ bias,
              int K, int lda, int ldb, int ldc)
{
    extern __shared__ uint16_t smh[];
    gemm_body<DT,OUT,EPI,BM,BN,WARPS_M,WARPS_N>(
        A, Bm, Cv, bias, K, lda, ldb, ldc, blockIdx.y*BM, blockIdx.x*BN, smh);
}

// grouped QKV: grid.y = 3*64, segment = by/64
__global__ __launch_bounds__(256, 2)
void qkv_k(const uint16_t* a0, const uint16_t* a1, const uint16_t* a2,
           const uint16_t* w0, const uint16_t* w1, const uint16_t* w2,
           uint16_t* c0, uint16_t* c1, uint16_t* c2,
           const float* p0, const float* p1, const float* p2)
{
    extern __shared__ uint16_t smh[];
    const int seg = blockIdx.y >> 6;
    const int mb  = blockIdx.y & 63;
    const uint16_t* A = (seg==0) ? a0 : (seg==1) ? a1 : a2;
    const uint16_t* W = (seg==0) ? w0 : (seg==1) ? w1 : w2;
    uint16_t*       C = (seg==0) ? c0 : (seg==1) ? c1 : c2;
    const float*    P = (seg==0) ? p0 : (seg==1) ? p1 : p2;
    gemm_body<0,1,1,128,128,2,4>(A, W, C, P, DD, DD, DD, DD, mb*128, blockIdx.x*128, smh);
}

// =================== fused flash attention (bf16 mma + ldmatrix) ===================
#define QP 72

__global__ __launch_bounds__(256, 2)
void flash_k(const __nv_bfloat16* __restrict__ qg, const __nv_bfloat16* __restrict__ kg,
             const __nv_bfloat16* __restrict__ vtg, __nv_bfloat16* __restrict__ ctx)
{
    extern __shared__ __nv_bfloat16 smb[];
    __nv_bfloat16* Qs = smb;                 // [128][QP], reused as P buffer
    __nv_bfloat16* Ks = smb + 128*QP;        // [2][64][QP]
    __nv_bfloat16* Vs = Ks + 2*64*QP;        // [2][64][QP]

    const int tid = threadIdx.x, wid = tid >> 5, lane = tid & 31;
    const int qr = lane >> 2, qc = lane & 3;
    const int bh = blockIdx.y;
    const int bb = bh / HH, hh = bh % HH;
    const int q0 = blockIdx.x * 128;

    const __nv_bfloat16* Qg = qg  + (size_t)(bb*SS + q0)*DD + hh*DHD;
    const __nv_bfloat16* Kg = kg  + (size_t)(bb*SS)*DD + hh*DHD;
    const __nv_bfloat16* Vg = vtg + (size_t)bh*DHD*SS;

    #pragma unroll
    for (int l = 0; l < 4; l++) {
        int ci = tid + l*256;
        int r = ci >> 3, c = ci & 7;
        cp16(Qs + r*QP + c*8, Qg + (size_t)r*DD + c*8);
    }
    CP_COMMIT();
    #pragma unroll
    for (int l = 0; l < 2; l++) {
        int ci = tid + l*256;
        int r = ci >> 3, c = ci & 7;
        cp16(Ks + r*QP + c*8, Kg + (size_t)r*DD + c*8);
        cp16(Vs + r*QP + c*8, Vg + (size_t)r*SS + c*8);
    }
    CP_COMMIT();

    cp_wait<1>();
    __syncthreads();

    // ldmatrix lane addressing
    const int war = wid*16 + ((lane & 8) ? 8 : 0) + (lane & 7);  // A-operand rows (Q / P)
    const int wac = (lane & 16) ? 8 : 0;
    const int kbr = ((lane & 16) ? 8 : 0) + (lane & 7);          // B-operand rows (K / V)
    const int kbc = (lane & 8) ? 8 : 0;

    uint32_t qf[4][4];
    #pragma unroll
    for (int ks = 0; ks < 4; ks++)
        ldmx4(qf[ks], Qs + (size_t)war*QP + ks*16 + wac);

    float m0v = -3.4e38f, m1v = -3.4e38f, l0 = 0.f, l1 = 0.f;
    float o[8][4];
    #pragma unroll
    for (int nt = 0; nt < 8; nt++)
        #pragma unroll
        for (int e = 0; e < 4; e++) o[nt][e] = 0.f;

    const int NJ = SS / 64;
    for (int j = 0; j < NJ; j++) {
        cp_wait<0>();
        __syncthreads();
        if (j + 1 < NJ) {
            __nv_bfloat16* Kn = Ks + ((j+1)&1)*64*QP;
            __nv_bfloat16* Vn = Vs + ((j+1)&1)*64*QP;
            const __nv_bfloat16* Kgn = Kg + (size_t)(j+1)*64*DD;
            const __nv_bfloat16* Vgn = Vg + (j+1)*64;
            #pragma unroll
            for (int l = 0; l < 2; l++) {
                int ci = tid + l*256;
                int r = ci >> 3, c = ci & 7;
                cp16(Kn + r*QP + c*8, Kgn + (size_t)r*DD + c*8);
                cp16(Vn + r*QP + c*8, Vgn + (size_t)r*SS + c*8);
            }
        }
        CP_COMMIT();

        const __nv_bfloat16* Kb = Ks + (j&1)*64*QP;
        const __nv_bfloat16* Vb = Vs + (j&1)*64*QP;

        // ---- S = Q @ K^T ----
        float s[8][4];
        #pragma unroll
        for (int nt = 0; nt < 8; nt++)
            #pragma unroll
            for (int e = 0; e < 4; e++) s[nt][e] = 0.f;
        #pragma unroll
        for (int ks = 0; ks < 4; ks++) {
            #pragma unroll
            for (int ntp = 0; ntp < 4; ntp++) {
                uint32_t t[4];
                ldmx4(t, Kb + (size_t)(kbr + ntp*16)*QP + ks*16 + kbc);
                mma_bf(s[2*ntp],   qf[ks], t);
                mma_bf(s[2*ntp+1], qf[ks], t+2);
            }
        }

        // ---- online softmax ----
        float mx0 = -3.4e38f, mx1 = -3.4e38f;
        #pragma unroll
        for (int nt = 0; nt < 8; nt++) {
            #pragma unroll
            for (int e = 0; e < 4; e++) s[nt][e] *= 0.125f;
            mx0 = fmaxf(mx0, fmaxf(s[nt][0], s[nt][1]));
            mx1 = fmaxf(mx1, fmaxf(s[nt][2], s[nt][3]));
        }
        #pragma unroll
        for (int off = 1; off <= 2; off <<= 1) {
            mx0 = fmaxf(mx0, __shfl_xor_sync(0xffffffffu, mx0, off));
            mx1 = fmaxf(mx1, __shfl_xor_sync(0xffffffffu, mx1, off));
        }
        float mn0 = fmaxf(m0v, mx0), mn1 = fmaxf(m1v, mx1);
        float a0 = __expf(m0v - mn0), a1 = __expf(m1v - mn1);
        m0v = mn0; m1v = mn1;
        float sum0 = 0.f, sum1 = 0.f;
        #pragma unroll
        for (int nt = 0; nt < 8; nt++) {
            s[nt][0] = __expf(s[nt][0] - mn0); sum0 += s[nt][0];
            s[nt][1] = __expf(s[nt][1] - mn0); sum0 += s[nt][1];
            s[nt][2] = __expf(s[nt][2] - mn1); sum1 += s[nt][2];
            s[nt][3] = __expf(s[nt][3] - mn1); sum1 += s[nt][3];
        }
        #pragma unroll
        for (int off = 1; off <= 2; off <<= 1) {
            sum0 += __shfl_xor_sync(0xffffffffu, sum0, off);
            sum1 += __shfl_xor_sync(0xffffffffu, sum1, off);
        }
        l0 = l0*a0 + sum0;
        l1 = l1*a1 + sum1;
        #pragma unroll
        for (int nt = 0; nt < 8; nt++) {
            o[nt][0] *= a0; o[nt][1] *= a0;
            o[nt][2] *= a1; o[nt][3] *= a1;
        }

        // ---- P -> smem bf16 (warp-private rows) ----
        __nv_bfloat16* Pw = Qs + (size_t)(wid*16)*QP;
        __syncwarp();
        #pragma unroll
        for (int nt = 0; nt < 8; nt++) {
            *reinterpret_cast<uint32_t*>(Pw + (size_t)qr*QP     + nt*8 + 2*qc) = pack_bf16(s[nt][0], s[nt][1]);
            *reinterpret_cast<uint32_t*>(Pw + (size_t)(qr+8)*QP + nt*8 + 2*qc) = pack_bf16(s[nt][2], s[nt][3]);
        }
        __syncwarp();

        // ---- O += P @ V ----
        #pragma unroll
        for (int ks = 0; ks < 4; ks++) {
            uint32_t af[4];
            ldmx4(af, Qs + (size_t)war*QP + ks*16 + wac);
            #pragma unroll
            for (int ntp = 0; ntp < 4; ntp++) {
                uint32_t t[4];
                ldmx4(t, Vb + (size_t)(kbr + ntp*16)*QP + ks*16 + kbc);
                mma_bf(o[2*ntp],   af, t);
                mma_bf(o[2*ntp+1], af, t+2);
            }
        }
        __syncwarp();
    }

    float inv0 = 1.f / l0, inv1 = 1.f / l1;
    const int r0 = q0 + wid*16 + qr;
    __nv_bfloat16* C0 = ctx + (size_t)(bb*SS + r0)*DD + hh*DHD + 2*qc;
    #pragma unroll
    for (int nt = 0; nt < 8; nt++) {
        *reinterpret_cast<uint32_t*>(C0 + nt*8)        = pack_bf16(o[nt][0]*inv0, o[nt][1]*inv0);
        *reinterpret_cast<uint32_t*>(C0 + 8*DD + nt*8) = pack_bf16(o[nt][2]*inv1, o[nt][3]*inv1);
    }
}

// =================== block reduce / LN ===================
__device__ __forceinline__ float block_reduce(float val, bool ismax) {
    __shared__ float sh[32];
    int lane = threadIdx.x & 31, w = threadIdx.x >> 5;
    #pragma unroll
    for (int off=16; off>0; off>>=1) {
        float o = __shfl_xor_sync(0xffffffffu, val, off);
        val = ismax ? fmaxf(val, o) : (val + o);
    }
    if (lane == 0) sh[w] = val;
    __syncthreads();
    int nw = blockDim.x >> 5;
    if (w == 0) {
        float v = (lane < nw) ? sh[lane] : (ismax ? -3.4e38f : 0.f);
        #pragma unroll
        for (int off=16; off>0; off>>=1) {
            float o = __shfl_xor_sync(0xffffffffu, v, off);
            v = ismax ? fmaxf(v, o) : (v + o);
        }
        if (lane == 0) sh[0] = v;
    }
    __syncthreads();
    float r = sh[0];
    __syncthreads();
    return r;
}

__global__ __launch_bounds__(256) void add_ln_k(
    const float* __restrict__ x, const float* __restrict__ res,
    const float* __restrict__ g, const float* __restrict__ b,
    __half* __restrict__ y)
{
    size_t base = (size_t)blockIdx.x * DD;
    int t = threadIdx.x;
    float v[3];
    float s = 0.f;
    #pragma unroll
    for (int i=0;i<3;i++){
        int c = t + i*256;
        v[i] = x[base + c] + res[base + c];
        s += v[i];
    }
    s = block_reduce(s, false);
    float mu = s * (1.0f/DD);
    float q = 0.f;
    #pragma unroll
    for (int i=0;i<3;i++){ float d = v[i]-mu; q += d*d; }
    q = block_reduce(q, false);
    float rstd = rsqrtf(q * (1.0f/DD) + 1e-5f);
    #pragma unroll
    for (int i=0;i<3;i++){
        int c = t + i*256;
        y[base + c] = __float2half_rn((v[i]-mu)*rstd*g[c] + b[c]);
    }
}

// =================== launch ===================
extern "C" void kernel_launch(void* const* d_in, const int* in_sizes, int n_in,
                              void* d_out, int out_size)
{
    const float* Q   = (const float*)d_in[0];
    const float* K   = (const float*)d_in[1];
    const float* V   = (const float*)d_in[2];
    const float* Wq  = (const float*)d_in[3];
    const float* bq  = (const float*)d_in[4];
    const float* Wk  = (const float*)d_in[5];
    const float* bk  = (const float*)d_in[6];
    const float* Wv  = (const float*)d_in[7];
    const float* bv  = (const float*)d_in[8];
    const float* Wo  = (const float*)d_in[9];
    const float* bo  = (const float*)d_in[10];
    const float* lng = (const float*)d_in[11];
    const float* lnb = (const float*)d_in[12];
    const float* W1  = (const float*)d_in[13];
    const float* b1  = (const float*)d_in[14];
    const float* W2  = (const float*)d_in[15];
    const float* b2  = (const float*)d_in[16];
    float* out = (float*)d_out;

    __nv_bfloat16 *xq,*xk,*xv,*qb,*kb,*vb,*vTb,*ctxb,*wqT,*wkT,*wvT,*woT;
    float *tmp;
    __half *h,*ff1,*w1T,*w2T;
    cudaGetSymbolAddress((void**)&xq,  g_xq);
    cudaGetSymbolAddress((void**)&xk,  g_xk);
    cudaGetSymbolAddress((void**)&xv,  g_xv);
    cudaGetSymbolAddress((void**)&qb,  g_qb);
    cudaGetSymbolAddress((void**)&kb,  g_kb);
    cudaGetSymbolAddress((void**)&vb,  g_vb);
    cudaGetSymbolAddress((void**)&vTb, g_vTb);
    cudaGetSymbolAddress((void**)&ctxb,g_ctxb);
    cudaGetSymbolAddress((void**)&tmp, g_tmp);
    cudaGetSymbolAddress((void**)&h,   g_h);
    cudaGetSymbolAddress((void**)&ff1, g_ff1);
    cudaGetSymbolAddress((void**)&wqT, g_wqT);
    cudaGetSymbolAddress((void**)&wkT, g_wkT);
    cudaGetSymbolAddress((void**)&wvT, g_wvT);
    cudaGetSymbolAddress((void**)&woT, g_woT);
    cudaGetSymbolAddress((void**)&w1T, g_w1T);
    cudaGetSymbolAddress((void**)&w2T, g_w2T);

    const int SM_128 = 3*(128+128)*40*2;        // 61440
    const int SM_64  = 3*(128+ 64)*40*2;        // 46080
    const int SM_FL  = (128*QP + 4*64*QP)*2;    // 55296
    cudaFuncSetAttribute((const void*)qkv_k, cudaFuncAttributeMaxDynamicSharedMemorySize, SM_128);
    cudaFuncSetAttribute((const void*)gemm16_k<0,0,1,128,64,4,2>, cudaFuncAttributeMaxDynamicSharedMemorySize, SM_64);
    cudaFuncSetAttribute((const void*)gemm16_k<1,2,2,128,128,2,4>, cudaFuncAttributeMaxDynamicSharedMemorySize, SM_128);
    cudaFuncSetAttribute((const void*)gemm16_k<1,0,1,128,64,4,2>, cudaFuncAttributeMaxDynamicSharedMemorySize, SM_64);
    cudaFuncSetAttribute((const void*)flash_k, cudaFuncAttributeMaxDynamicSharedMemorySize, SM_FL);

    const int NEL = BB*SS*DD;
    dim3 tb(32, 8);

    // 0) inputs -> bf16 ; weights -> transposed bf16 / fp16
    f2b_k<<<NEL/1024, 256>>>(Q, xq);
    f2b_k<<<NEL/1024, 256>>>(K, xk);
    f2b_k<<<NEL/1024, 256>>>(V, xv);
    transpose_t<0><<<dim3(DD/32, DD/32),  tb>>>(Wq, wqT, DD, DD);
    transpose_t<0><<<dim3(DD/32, DD/32),  tb>>>(Wk, wkT, DD, DD);
    transpose_t<0><<<dim3(DD/32, DD/32),  tb>>>(Wv, wvT, DD, DD);
    transpose_t<0><<<dim3(DD/32, DD/32),  tb>>>(Wo, woT, DD, DD);
    transpose_t<1><<<dim3(DFF/32, DD/32), tb>>>(W1, w1T, DD, DFF);
    transpose_t<1><<<dim3(DD/32, DFF/32), tb>>>(W2, w2T, DFF, DD);

    // 1) grouped QKV projection (one launch, 1152 blocks)
    qkv_k<<<dim3(DD/128, 3*(MROWS/128)), 256, SM_128>>>(
        (const uint16_t*)xq, (const uint16_t*)xk, (const uint16_t*)xv,
        (const uint16_t*)wqT, (const uint16_t*)wkT, (const uint16_t*)wvT,
        (uint16_t*)qb, (uint16_t*)kb, (uint16_t*)vb,
        bq, bk, bv);

    // 1b) v -> vT
    vtrans_k<<<dim3(SS/32, DHD/32, BB*HH), tb>>>(vb, vTb);

    // 2-4) fused flash attention -> ctx (bf16)
    flash_k<<<dim3(SS/128, BB*HH), 256, SM_FL>>>(qb, kb, vTb, ctxb);

    // 5) attn_out = ctx @ Wo^T + bo (bf16 -> fp32), BN=64 tiles
    gemm16_k<0,0,1,128,64,4,2><<<dim3(DD/64, MROWS/128), 256, SM_64>>>(
        (const uint16_t*)ctxb, (const uint16_t*)woT, tmp, bo, DD, DD, DD, DD);

    // 6) h = fp16(LN(Q + attn_out))
    add_ln_k<<<MROWS, 256>>>(tmp, Q, lng, lnb, h);

    // 7) ff1 = fp16(gelu(h @ W1^T + b1))
    gemm16_k<1,2,2,128,128,2,4><<<dim3(DFF/128, MROWS/128), 256, SM_128>>>(
        (const uint16_t*)h, (const uint16_t*)w1T, ff1, b1, DD, DD, DD, DFF);

    // 8) out = ff1 @ W2^T + b2 (fp16 -> fp32), BN=64 tiles
    gemm16_k<1,0,1,128,64,4,2><<<dim3(DD/64, MROWS/128), 256, SM_64>>>(
        (const uint16_t*)ff1, (const uint16_t*)w2T, out, b2, DFF, DFF, DFF, DD);
}

// round 13
// speedup vs baseline: 6.4631x; 1.0374x over previous
#include <cuda_runtime.h>
#include <cuda_bf16.h>
#include <cuda_fp16.h>
#include <math.h>
#include <stdint.h>

// Problem constants
#define BB   4
#define SS   2048
#define DD   768
#define HH   12
#define DHD  64
#define DFF  3072
#define MROWS (BB*SS)          // 8192

// -------- scratch (device globals; no allocations allowed) --------
static __device__ __align__(16) __nv_bfloat16 g_xq [(size_t)BB*SS*DD];
static __device__ __align__(16) __nv_bfloat16 g_xk [(size_t)BB*SS*DD];
static __device__ __align__(16) __nv_bfloat16 g_xv [(size_t)BB*SS*DD];
static __device__ __align__(16) __nv_bfloat16 g_qb [(size_t)BB*SS*DD];
static __device__ __align__(16) __nv_bfloat16 g_kb [(size_t)BB*SS*DD];
static __device__ __align__(16) __nv_bfloat16 g_vb [(size_t)BB*SS*DD];
static __device__ __align__(16) __nv_bfloat16 g_vTb[(size_t)BB*HH*DHD*SS];
static __device__ __align__(16) __nv_bfloat16 g_ctxb[(size_t)BB*SS*DD];
static __device__ __align__(16) float  g_tmp[(size_t)BB*SS*DD];
static __device__ __align__(16) __half g_h  [(size_t)BB*SS*DD];
static __device__ __align__(16) __half g_ff1[(size_t)MROWS*DFF];
static __device__ __align__(16) __nv_bfloat16 g_wqT[(size_t)DD*DD];
static __device__ __align__(16) __nv_bfloat16 g_wkT[(size_t)DD*DD];
static __device__ __align__(16) __nv_bfloat16 g_wvT[(size_t)DD*DD];
static __device__ __align__(16) __nv_bfloat16 g_woT[(size_t)DD*DD];
static __device__ __align__(16) __half g_w1T[(size_t)DFF*DD];
static __device__ __align__(16) __half g_w2T[(size_t)DD*DFF];

__device__ __forceinline__ float gelu_exact(float x) {
    return 0.5f * x * (1.0f + erff(x * 0.7071067811865476f));
}

// ---------------- helpers ----------------
__device__ __forceinline__ uint32_t pack_bf16(float lo, float hi) {
    uint32_t r;
    asm("cvt.rn.bf16x2.f32 %0, %1, %2;" : "=r"(r) : "f"(hi), "f"(lo));
    return r;
}
__device__ __forceinline__ uint32_t pack_f16(float lo, float hi) {
    uint32_t r;
    asm("cvt.rn.f16x2.f32 %0, %1, %2;" : "=r"(r) : "f"(hi), "f"(lo));
    return r;
}
__device__ __forceinline__ void mma_bf(float* c, const uint32_t* a, const uint32_t* b) {
    asm volatile("mma.sync.aligned.m16n8k16.row.col.f32.bf16.bf16.f32 "
        "{%0,%1,%2,%3}, {%4,%5,%6,%7}, {%8,%9}, {%0,%1,%2,%3};"
        : "+f"(c[0]), "+f"(c[1]), "+f"(c[2]), "+f"(c[3])
        : "r"(a[0]), "r"(a[1]), "r"(a[2]), "r"(a[3]), "r"(b[0]), "r"(b[1]));
}
__device__ __forceinline__ void mma_fp(float* c, const uint32_t* a, const uint32_t* b) {
    asm volatile("mma.sync.aligned.m16n8k16.row.col.f32.f16.f16.f32 "
        "{%0,%1,%2,%3}, {%4,%5,%6,%7}, {%8,%9}, {%0,%1,%2,%3};"
        : "+f"(c[0]), "+f"(c[1]), "+f"(c[2]), "+f"(c[3])
        : "r"(a[0]), "r"(a[1]), "r"(a[2]), "r"(a[3]), "r"(b[0]), "r"(b[1]));
}
__device__ __forceinline__ void ldmx4(uint32_t* r, const void* p) {
    uint32_t a = (uint32_t)__cvta_generic_to_shared(p);
    asm volatile("ldmatrix.sync.aligned.m8n8.x4.shared.b16 {%0,%1,%2,%3}, [%4];"
        : "=r"(r[0]), "=r"(r[1]), "=r"(r[2]), "=r"(r[3]) : "r"(a));
}
template<int N> __device__ __forceinline__ void cp_wait() {
    asm volatile("cp.async.wait_group %0;" :: "n"(N));
}
#define CP_COMMIT() asm volatile("cp.async.commit_group;")
__device__ __forceinline__ void cp16(void* smem_dst, const void* gsrc) {
    uint32_t d = (uint32_t)__cvta_generic_to_shared(smem_dst);
    asm volatile("cp.async.cg.shared.global [%0], [%1], 16;" :: "r"(d), "l"(gsrc));
}

// =================== fused fp32->bf16 for Q,K,V ===================
__global__ __launch_bounds__(256) void f2b3_k(
    const float* __restrict__ x0, const float* __restrict__ x1, const float* __restrict__ x2,
    __nv_bfloat16* __restrict__ y0, __nv_bfloat16* __restrict__ y1, __nv_bfloat16* __restrict__ y2)
{
    const int seg = blockIdx.y;
    const float* x = (seg==0) ? x0 : (seg==1) ? x1 : x2;
    __nv_bfloat16* y = (seg==0) ? y0 : (seg==1) ? y1 : y2;
    size_t i = ((size_t)blockIdx.x*256 + threadIdx.x) * 4;
    float4 v = *reinterpret_cast<const float4*>(x + i);
    uint2 o;
    o.x = pack_bf16(v.x, v.y);
    o.y = pack_bf16(v.z, v.w);
    *reinterpret_cast<uint2*>(y + i) = o;
}

// =================== transposes ===================
// 4 DDxDD weight transposes fused (bf16 out)
__global__ __launch_bounds__(256) void wtrans4_k(
    const float* __restrict__ w0, const float* __restrict__ w1,
    const float* __restrict__ w2, const float* __restrict__ w3,
    __nv_bfloat16* __restrict__ d0, __nv_bfloat16* __restrict__ d1,
    __nv_bfloat16* __restrict__ d2, __nv_bfloat16* __restrict__ d3)
{
    __shared__ float tile[32][33];
    const int z = blockIdx.z;
    const float* src = (z==0)?w0:(z==1)?w1:(z==2)?w2:w3;
    __nv_bfloat16* dst = (z==0)?d0:(z==1)?d1:(z==2)?d2:d3;
    const int c0 = blockIdx.x*32, r0 = blockIdx.y*32;
    const int x = threadIdx.x, y = threadIdx.y;
    #pragma unroll
    for (int i = 0; i < 32; i += 8) tile[y+i][x] = src[(size_t)(r0+y+i)*DD + c0+x];
    __syncthreads();
    #pragma unroll
    for (int i = 0; i < 32; i += 8)
        dst[(size_t)(c0+y+i)*DD + r0+x] = __float2bfloat16_rn(tile[x][y+i]);
}

// fp16 transpose (for W1/W2)
__global__ __launch_bounds__(256) void htrans_k(const float* __restrict__ src,
                                                __half* __restrict__ dst, int R, int C)
{
    __shared__ float tile[32][33];
    const int c0 = blockIdx.x*32, r0 = blockIdx.y*32;
    const int x = threadIdx.x, y = threadIdx.y;
    #pragma unroll
    for (int i = 0; i < 32; i += 8) tile[y+i][x] = src[(size_t)(r0+y+i)*C + c0+x];
    __syncthreads();
    #pragma unroll
    for (int i = 0; i < 32; i += 8)
        dst[(size_t)(c0+y+i)*R + r0+x] = __float2half_rn(tile[x][y+i]);
}

__global__ __launch_bounds__(256) void vtrans_k(const __nv_bfloat16* __restrict__ v,
                                                __nv_bfloat16* __restrict__ vt)
{
    __shared__ __nv_bfloat16 tile[32][34];
    const int z = blockIdx.z, bb = z/HH, hh = z%HH;
    const int s0 = blockIdx.x*32, d0 = blockIdx.y*32;
    const int x = threadIdx.x, y = threadIdx.y;
    #pragma unroll
    for (int i = 0; i < 32; i += 8)
        tile[y+i][x] = v[(size_t)(bb*SS + s0 + y+i)*DD + hh*DHD + d0 + x];
    __syncthreads();
    #pragma unroll
    for (int i = 0; i < 32; i += 8)
        vt[(size_t)(z*DHD + d0 + y+i)*SS + s0 + x] = tile[x][y+i];
}

// =================== 16-bit GEMM body (ldmatrix + 4-stage) ===================
template<int DT, int OUT, int EPI, int BM, int BN, int WARPS_M, int WARPS_N>
__device__ __forceinline__ void gemm_body(
    const uint16_t* __restrict__ A, const uint16_t* __restrict__ Bm,
    void* __restrict__ Cv, const float* __restrict__ bias,
    int K, int lda, int ldb, int ldc, int m0, int n0, uint16_t* smh)
{
    constexpr int S = 4, PITCH = 40;
    constexpr int WM = BM/WARPS_M, WN = BN/WARPS_N;
    constexpr int MT = WM/16, NT = WN/8;
    uint16_t* sA = smh;
    uint16_t* sB = smh + (size_t)S*BM*PITCH;

    const int tid = threadIdx.x;
    const uint16_t* Ab = A  + (size_t)m0*lda;
    const uint16_t* Bb = Bm + (size_t)n0*ldb;
    const int KT = K / 32;

    auto load_stage = [&](int kt, int st) {
        uint16_t* dA = sA + (size_t)st*BM*PITCH;
        uint16_t* dB = sB + (size_t)st*BN*PITCH;
        #pragma unroll
        for (int l = 0; l < (BM*4)/256; l++) {
            int ci = tid + l*256;
            int r = ci >> 2, c = ci & 3;
            cp16(dA + r*PITCH + c*8, Ab + (size_t)r*lda + kt*32 + c*8);
        }
        #pragma unroll
        for (int l = 0; l < (BN*4)/256; l++) {
            int ci = tid + l*256;
            int r = ci >> 2, c = ci & 3;
            cp16(dB + r*PITCH + c*8, Bb + (size_t)r*ldb + kt*32 + c*8);
        }
    };

    #pragma unroll
    for (int s = 0; s < S-1; s++) { if (s < KT) load_stage(s, s); CP_COMMIT(); }

    const int wid = tid >> 5, lane = tid & 31;
    const int wm = (wid / WARPS_N) * WM;
    const int wn = (wid % WARPS_N) * WN;
    const int qr = lane >> 2, qc = lane & 3;
    const int aar = wm + ((lane & 8) ? 8 : 0) + (lane & 7);
    const int aac = (lane & 16) ? 8 : 0;
    const int bbr = wn + ((lane & 16) ? 8 : 0) + (lane & 7);
    const int bbc = (lane & 8) ? 8 : 0;

    float acc[MT][NT][4];
    #pragma unroll
    for (int i=0;i<MT;i++) for (int j=0;j<NT;j++) for (int e=0;e<4;e++) acc[i][j][e]=0.f;

    for (int kt = 0; kt < KT; kt++) {
        cp_wait<S-2>();
        __syncthreads();
        const int nk = kt + S - 1;
        if (nk < KT) load_stage(nk, nk % S);
        CP_COMMIT();

        const uint16_t* As = sA + (size_t)(kt % S)*BM*PITCH;
        const uint16_t* Bs = sB + (size_t)(kt % S)*BN*PITCH;
        #pragma unroll
        for (int ks = 0; ks < 2; ks++) {
            uint32_t af[MT][4];
            #pragma unroll
            for (int mt = 0; mt < MT; mt++)
                ldmx4(af[mt], As + (size_t)(aar + mt*16)*PITCH + ks*16 + aac);
            #pragma unroll
            for (int ntp = 0; ntp < NT/2; ntp++) {
                uint32_t t[4];
                ldmx4(t, Bs + (size_t)(bbr + ntp*16)*PITCH + ks*16 + bbc);
                #pragma unroll
                for (int mt = 0; mt < MT; mt++) {
                    if (DT == 0) { mma_bf(acc[mt][2*ntp], af[mt], t); mma_bf(acc[mt][2*ntp+1], af[mt], t+2); }
                    else         { mma_fp(acc[mt][2*ntp], af[mt], t); mma_fp(acc[mt][2*ntp+1], af[mt], t+2); }
                }
            }
        }
    }

    #pragma unroll
    for (int mt = 0; mt < MT; mt++) {
        #pragma unroll
        for (int nt = 0; nt < NT; nt++) {
            const int cc = n0 + wn + nt*8 + qc*2;
            float b0 = __ldg(&bias[cc]), b1 = __ldg(&bias[cc+1]);
            float x0 = acc[mt][nt][0] + b0, x1 = acc[mt][nt][1] + b1;
            float x2 = acc[mt][nt][2] + b0, x3 = acc[mt][nt][3] + b1;
            if (EPI == 2) {
                x0 = gelu_exact(x0); x1 = gelu_exact(x1);
                x2 = gelu_exact(x2); x3 = gelu_exact(x3);
            }
            const size_t r0 = (size_t)(m0 + wm + mt*16 + qr);
            if (OUT == 0) {
                float* Cf = (float*)Cv;
                *reinterpret_cast<float2*>(Cf + r0*ldc + cc)     = make_float2(x0, x1);
                *reinterpret_cast<float2*>(Cf + (r0+8)*ldc + cc) = make_float2(x2, x3);
            } else if (OUT == 1) {
                __nv_bfloat16* Cb = (__nv_bfloat16*)Cv;
                *reinterpret_cast<uint32_t*>(Cb + r0*ldc + cc)     = pack_bf16(x0, x1);
                *reinterpret_cast<uint32_t*>(Cb + (r0+8)*ldc + cc) = pack_bf16(x2, x3);
            } else {
                __half* Ch = (__half*)Cv;
                *reinterpret_cast<uint32_t*>(Ch + r0*ldc + cc)     = pack_f16(x0, x1);
                *reinterpret_cast<uint32_t*>(Ch + (r0+8)*ldc + cc) = pack_f16(x2, x3);
            }
        }
    }
}

template<int DT, int OUT, int EPI, int BM, int BN, int WARPS_M, int WARPS_N>
__global__ __launch_bounds__(256, 2)
void gemm16_k(const uint16_t* __restrict__ A, const uint16_t* __restrict__ Bm,
              void* __restrict__ Cv, const float* __restrict__ bias,
              int K, int lda, int ldb, int ldc)
{
    extern __shared__ uint16_t smh[];
    gemm_body<DT,OUT,EPI,BM,BN,WARPS_M,WARPS_N>(
        A, Bm, Cv, bias, K, lda, ldb, ldc, blockIdx.y*BM, blockIdx.x*BN, smh);
}

// grouped QKV
__global__ __launch_bounds__(256, 2)
void qkv_k(const uint16_t* a0, const uint16_t* a1, const uint16_t* a2,
           const uint16_t* w0, const uint16_t* w1, const uint16_t* w2,
           uint16_t* c0, uint16_t* c1, uint16_t* c2,
           const float* p0, const float* p1, const float* p2)
{
    extern __shared__ uint16_t smh[];
    const int seg = blockIdx.y >> 6;
    const int mb  = blockIdx.y & 63;
    const uint16_t* A = (seg==0) ? a0 : (seg==1) ? a1 : a2;
    const uint16_t* W = (seg==0) ? w0 : (seg==1) ? w1 : w2;
    uint16_t*       C = (seg==0) ? c0 : (seg==1) ? c1 : c2;
    const float*    P = (seg==0) ? p0 : (seg==1) ? p1 : p2;
    gemm_body<0,1,1,128,128,2,4>(A, W, C, P, DD, DD, DD, DD, mb*128, blockIdx.x*128, smh);
}

// =================== fused flash attention (register-P, depth-2 prefetch) ===================
#define QP 72

__global__ __launch_bounds__(256, 2)
void flash_k(const __nv_bfloat16* __restrict__ qg, const __nv_bfloat16* __restrict__ kg,
             const __nv_bfloat16* __restrict__ vtg, __nv_bfloat16* __restrict__ ctx)
{
    extern __shared__ __nv_bfloat16 smb[];
    __nv_bfloat16* Qs = smb;                 // [128][QP]
    __nv_bfloat16* Ks = smb + 128*QP;        // [3][64][QP]
    __nv_bfloat16* Vs = Ks + 3*64*QP;        // [3][64][QP]

    const int tid = threadIdx.x, wid = tid >> 5, lane = tid & 31;
    const int qr = lane >> 2, qc = lane & 3;
    const int bh = blockIdx.y;
    const int bb = bh / HH, hh = bh % HH;
    const int q0 = blockIdx.x * 128;

    const __nv_bfloat16* Qg = qg  + (size_t)(bb*SS + q0)*DD + hh*DHD;
    const __nv_bfloat16* Kg = kg  + (size_t)(bb*SS)*DD + hh*DHD;
    const __nv_bfloat16* Vg = vtg + (size_t)bh*DHD*SS;

    auto load_kv = [&](int j) {
        __nv_bfloat16* Kn = Ks + (j%3)*64*QP;
        __nv_bfloat16* Vn = Vs + (j%3)*64*QP;
        const __nv_bfloat16* Kgn = Kg + (size_t)j*64*DD;
        const __nv_bfloat16* Vgn = Vg + j*64;
        #pragma unroll
        for (int l = 0; l < 2; l++) {
            int ci = tid + l*256;
            int r = ci >> 3, c = ci & 7;
            cp16(Kn + r*QP + c*8, Kgn + (size_t)r*DD + c*8);
            cp16(Vn + r*QP + c*8, Vgn + (size_t)r*SS + c*8);
        }
    };

    // Q stage
    #pragma unroll
    for (int l = 0; l < 4; l++) {
        int ci = tid + l*256;
        int r = ci >> 3, c = ci & 7;
        cp16(Qs + r*QP + c*8, Qg + (size_t)r*DD + c*8);
    }
    CP_COMMIT();
    load_kv(0); CP_COMMIT();
    load_kv(1); CP_COMMIT();

    cp_wait<2>();          // Q done
    __syncthreads();

    const int war = wid*16 + ((lane & 8) ? 8 : 0) + (lane & 7);
    const int wac = (lane & 16) ? 8 : 0;
    const int kbr = ((lane & 16) ? 8 : 0) + (lane & 7);
    const int kbc = (lane & 8) ? 8 : 0;

    uint32_t qf[4][4];
    #pragma unroll
    for (int ks = 0; ks < 4; ks++)
        ldmx4(qf[ks], Qs + (size_t)war*QP + ks*16 + wac);

    float m0v = -3.4e38f, m1v = -3.4e38f, l0 = 0.f, l1 = 0.f;
    float o[8][4];
    #pragma unroll
    for (int nt = 0; nt < 8; nt++)
        #pragma unroll
        for (int e = 0; e < 4; e++) o[nt][e] = 0.f;

    const int NJ = SS / 64;
    for (int j = 0; j < NJ; j++) {
        cp_wait<1>();        // KV(j) landed; KV(j+1) may be in flight
        __syncthreads();
        if (j + 2 < NJ) load_kv(j + 2);
        CP_COMMIT();

        const __nv_bfloat16* Kb = Ks + (j%3)*64*QP;
        const __nv_bfloat16* Vb = Vs + (j%3)*64*QP;

        // ---- S = Q @ K^T ----
        float s[8][4];
        #pragma unroll
        for (int nt = 0; nt < 8; nt++)
            #pragma unroll
            for (int e = 0; e < 4; e++) s[nt][e] = 0.f;
        #pragma unroll
        for (int ks = 0; ks < 4; ks++) {
            #pragma unroll
            for (int ntp = 0; ntp < 4; ntp++) {
                uint32_t t[4];
                ldmx4(t, Kb + (size_t)(kbr + ntp*16)*QP + ks*16 + kbc);
                mma_bf(s[2*ntp],   qf[ks], t);
                mma_bf(s[2*ntp+1], qf[ks], t+2);
            }
        }

        // ---- online softmax ----
        float mx0 = -3.4e38f, mx1 = -3.4e38f;
        #pragma unroll
        for (int nt = 0; nt < 8; nt++) {
            #pragma unroll
            for (int e = 0; e < 4; e++) s[nt][e] *= 0.125f;
            mx0 = fmaxf(mx0, fmaxf(s[nt][0], s[nt][1]));
            mx1 = fmaxf(mx1, fmaxf(s[nt][2], s[nt][3]));
        }
        #pragma unroll
        for (int off = 1; off <= 2; off <<= 1) {
            mx0 = fmaxf(mx0, __shfl_xor_sync(0xffffffffu, mx0, off));
            mx1 = fmaxf(mx1, __shfl_xor_sync(0xffffffffu, mx1, off));
        }
        float mn0 = fmaxf(m0v, mx0), mn1 = fmaxf(m1v, mx1);
        float a0 = __expf(m0v - mn0), a1 = __expf(m1v - mn1);
        m0v = mn0; m1v = mn1;
        float sum0 = 0.f, sum1 = 0.f;
        #pragma unroll
        for (int nt = 0; nt < 8; nt++) {
            s[nt][0] = __expf(s[nt][0] - mn0); sum0 += s[nt][0];
            s[nt][1] = __expf(s[nt][1] - mn0); sum0 += s[nt][1];
            s[nt][2] = __expf(s[nt][2] - mn1); sum1 += s[nt][2];
            s[nt][3] = __expf(s[nt][3] - mn1); sum1 += s[nt][3];
        }
        #pragma unroll
        for (int off = 1; off <= 2; off <<= 1) {
            sum0 += __shfl_xor_sync(0xffffffffu, sum0, off);
            sum1 += __shfl_xor_sync(0xffffffffu, sum1, off);
        }
        l0 = l0*a0 + sum0;
        l1 = l1*a1 + sum1;
        #pragma unroll
        for (int nt = 0; nt < 8; nt++) {
            o[nt][0] *= a0; o[nt][1] *= a0;
            o[nt][2] *= a1; o[nt][3] *= a1;
        }

        // ---- O += P @ V : P fragments built directly from S registers ----
        #pragma unroll
        for (int ks = 0; ks < 4; ks++) {
            uint32_t af[4] = {
                pack_bf16(s[2*ks][0],   s[2*ks][1]),
                pack_bf16(s[2*ks][2],   s[2*ks][3]),
                pack_bf16(s[2*ks+1][0], s[2*ks+1][1]),
                pack_bf16(s[2*ks+1][2], s[2*ks+1][3]) };
            #pragma unroll
            for (int ntp = 0; ntp < 4; ntp++) {
                uint32_t t[4];
                ldmx4(t, Vb + (size_t)(kbr + ntp*16)*QP + ks*16 + kbc);
                mma_bf(o[2*ntp],   af, t);
                mma_bf(o[2*ntp+1], af, t+2);
            }
        }
    }

    float inv0 = 1.f / l0, inv1 = 1.f / l1;
    const int r0 = q0 + wid*16 + qr;
    __nv_bfloat16* C0 = ctx + (size_t)(bb*SS + r0)*DD + hh*DHD + 2*qc;
    #pragma unroll
    for (int nt = 0; nt < 8; nt++) {
        *reinterpret_cast<uint32_t*>(C0 + nt*8)        = pack_bf16(o[nt][0]*inv0, o[nt][1]*inv0);
        *reinterpret_cast<uint32_t*>(C0 + 8*DD + nt*8) = pack_bf16(o[nt][2]*inv1, o[nt][3]*inv1);
    }
}

// =================== block reduce / LN ===================
__device__ __forceinline__ float block_reduce(float val, bool ismax) {
    __shared__ float sh[32];
    int lane = threadIdx.x & 31, w = threadIdx.x >> 5;
    #pragma unroll
    for (int off=16; off>0; off>>=1) {
        float o = __shfl_xor_sync(0xffffffffu, val, off);
        val = ismax ? fmaxf(val, o) : (val + o);
    }
    if (lane == 0) sh[w] = val;
    __syncthreads();
    int nw = blockDim.x >> 5;
    if (w == 0) {
        float v = (lane < nw) ? sh[lane] : (ismax ? -3.4e38f : 0.f);
        #pragma unroll
        for (int off=16; off>0; off>>=1) {
            float o = __shfl_xor_sync(0xffffffffu, v, off);
            v = ismax ? fmaxf(v, o) : (v + o);
        }
        if (lane == 0) sh[0] = v;
    }
    __syncthreads();
    float r = sh[0];
    __syncthreads();
    return r;
}

__global__ __launch_bounds__(256) void add_ln_k(
    const float* __restrict__ x, const float* __restrict__ res,
    const float* __restrict__ g, const float* __restrict__ b,
    __half* __restrict__ y)
{
    size_t base = (size_t)blockIdx.x * DD;
    int t = threadIdx.x;
    float v[3];
    float s = 0.f;
    #pragma unroll
    for (int i=0;i<3;i++){
        int c = t + i*256;
        v[i] = x[base + c] + res[base + c];
        s += v[i];
    }
    s = block_reduce(s, false);
    float mu = s * (1.0f/DD);
    float q = 0.f;
    #pragma unroll
    for (int i=0;i<3;i++){ float d = v[i]-mu; q += d*d; }
    q = block_reduce(q, false);
    float rstd = rsqrtf(q * (1.0f/DD) + 1e-5f);
    #pragma unroll
    for (int i=0;i<3;i++){
        int c = t + i*256;
        y[base + c] = __float2half_rn((v[i]-mu)*rstd*g[c] + b[c]);
    }
}

// =================== launch ===================
extern "C" void kernel_launch(void* const* d_in, const int* in_sizes, int n_in,
                              void* d_out, int out_size)
{
    const float* Q   = (const float*)d_in[0];
    const float* K   = (const float*)d_in[1];
    const float* V   = (const float*)d_in[2];
    const float* Wq  = (const float*)d_in[3];
    const float* bq  = (const float*)d_in[4];
    const float* Wk  = (const float*)d_in[5];
    const float* bk  = (const float*)d_in[6];
    const float* Wv  = (const float*)d_in[7];
    const float* bv  = (const float*)d_in[8];
    const float* Wo  = (const float*)d_in[9];
    const float* bo  = (const float*)d_in[10];
    const float* lng = (const float*)d_in[11];
    const float* lnb = (const float*)d_in[12];
    const float* W1  = (const float*)d_in[13];
    const float* b1  = (const float*)d_in[14];
    const float* W2  = (const float*)d_in[15];
    const float* b2  = (const float*)d_in[16];
    float* out = (float*)d_out;

    __nv_bfloat16 *xq,*xk,*xv,*qb,*kb,*vb,*vTb,*ctxb,*wqT,*wkT,*wvT,*woT;
    float *tmp;
    __half *h,*ff1,*w1T,*w2T;
    cudaGetSymbolAddress((void**)&xq,  g_xq);
    cudaGetSymbolAddress((void**)&xk,  g_xk);
    cudaGetSymbolAddress((void**)&xv,  g_xv);
    cudaGetSymbolAddress((void**)&qb,  g_qb);
    cudaGetSymbolAddress((void**)&kb,  g_kb);
    cudaGetSymbolAddress((void**)&vb,  g_vb);
    cudaGetSymbolAddress((void**)&vTb, g_vTb);
    cudaGetSymbolAddress((void**)&ctxb,g_ctxb);
    cudaGetSymbolAddress((void**)&tmp, g_tmp);
    cudaGetSymbolAddress((void**)&h,   g_h);
    cudaGetSymbolAddress((void**)&ff1, g_ff1);
    cudaGetSymbolAddress((void**)&wqT, g_wqT);
    cudaGetSymbolAddress((void**)&wkT, g_wkT);
    cudaGetSymbolAddress((void**)&wvT, g_wvT);
    cudaGetSymbolAddress((void**)&woT, g_woT);
    cudaGetSymbolAddress((void**)&w1T, g_w1T);
    cudaGetSymbolAddress((void**)&w2T, g_w2T);

    const int SM_128 = 4*(128+128)*40*2;        // 81920
    const int SM_64  = 4*(128+ 64)*40*2;        // 61440
    const int SM_FL  = (128*QP + 6*64*QP)*2;    // 73728
    cudaFuncSetAttribute((const void*)qkv_k, cudaFuncAttributeMaxDynamicSharedMemorySize, SM_128);
    cudaFuncSetAttribute((const void*)gemm16_k<0,0,1,128,64,4,2>, cudaFuncAttributeMaxDynamicSharedMemorySize, SM_64);
    cudaFuncSetAttribute((const void*)gemm16_k<1,2,2,128,128,2,4>, cudaFuncAttributeMaxDynamicSharedMemorySize, SM_128);
    cudaFuncSetAttribute((const void*)gemm16_k<1,0,1,128,64,4,2>, cudaFuncAttributeMaxDynamicSharedMemorySize, SM_64);
    cudaFuncSetAttribute((const void*)flash_k, cudaFuncAttributeMaxDynamicSharedMemorySize, SM_FL);

    const int NEL = BB*SS*DD;
    dim3 tb(32, 8);

    // 0) inputs -> bf16 (fused); weight transposes (fused bf16 x4; fp16 x2)
    f2b3_k<<<dim3(NEL/1024, 3), 256>>>(Q, K, V, xq, xk, xv);
    wtrans4_k<<<dim3(DD/32, DD/32, 4), tb>>>(Wq, Wk, Wv, Wo, wqT, wkT, wvT, woT);
    htrans_k<<<dim3(DFF/32, DD/32), tb>>>(W1, w1T, DD, DFF);
    htrans_k<<<dim3(DD/32, DFF/32), tb>>>(W2, w2T, DFF, DD);

    // 1) grouped QKV projection
    qkv_k<<<dim3(DD/128, 3*(MROWS/128)), 256, SM_128>>>(
        (const uint16_t*)xq, (const uint16_t*)xk, (const uint16_t*)xv,
        (const uint16_t*)wqT, (const uint16_t*)wkT, (const uint16_t*)wvT,
        (uint16_t*)qb, (uint16_t*)kb, (uint16_t*)vb,
        bq, bk, bv);

    // 1b) v -> vT
    vtrans_k<<<dim3(SS/32, DHD/32, BB*HH), tb>>>(vb, vTb);

    // 2-4) fused flash attention -> ctx (bf16)
    flash_k<<<dim3(SS/128, BB*HH), 256, SM_FL>>>(qb, kb, vTb, ctxb);

    // 5) attn_out = ctx @ Wo^T + bo (bf16 -> fp32)
    gemm16_k<0,0,1,128,64,4,2><<<dim3(DD/64, MROWS/128), 256, SM_64>>>(
        (const uint16_t*)ctxb, (const uint16_t*)woT, tmp, bo, DD, DD, DD, DD);

    // 6) h = fp16(LN(Q + attn_out))
    add_ln_k<<<MROWS, 256>>>(tmp, Q, lng, lnb, h);

    // 7) ff1 = fp16(gelu(h @ W1^T + b1))
    gemm16_k<1,2,2,128,128,2,4><<<dim3(DFF/128, MROWS/128), 256, SM_128>>>(
        (const uint16_t*)h, (const uint16_t*)w1T, ff1, b1, DD, DD, DD, DFF);

    // 8) out = ff1 @ W2^T + b2 (fp16 -> fp32)
    gemm16_k<1,0,1,128,64,4,2><<<dim3(DD/64, MROWS/128), 256, SM_64>>>(
        (const uint16_t*)ff1, (const uint16_t*)w2T, out, b2, DFF, DFF, DFF, DD);
}